// round 9
// baseline (speedup 1.0000x reference)
#include <cuda_runtime.h>
#include <cuda_bf16.h>
#include <cstdint>
#include <math.h>

// Problem constants
#define NN 50000
#define EE 400000
#define GG 64
#define IN_CH 128
#define HID 64
#define NHEAD 4
#define CH256 256   // NHEAD*HID
#define NPB_EDGE 8  // dst nodes per edge-kernel block

typedef unsigned long long ull;

// ---------------- scratch (static __device__ globals; no allocation) ----------
__device__ float  g_xl[NN * CH256];     // 51.2 MB
__device__ float  g_xr[NN * CH256];     // 51.2 MB
__device__ float  g_h [NN * HID];       // 12.8 MB
__device__ int    g_hist[NN];
__device__ int    g_off [NN + 1];
__device__ int    g_cur [NN];
__device__ int    g_csr_src[EE];
__device__ float4 g_csr_eap[EE];
__device__ float  g_pool[GG * HID];
__device__ float  g_cnt [GG];

// ---------------- packed f32x2 helpers ------------------------------------------
#define FFMA2(d, a, b) \
    asm("fma.rn.f32x2 %0, %1, %2, %0;" : "+l"(d) : "l"(a), "l"(b))
#define DUP2(d, f) \
    asm("mov.b64 %0, {%1, %1};" : "=l"(d) : "f"(f))
__device__ __forceinline__ float f2lo(ull v) { return __uint_as_float((uint32_t)v); }
__device__ __forceinline__ float f2hi(ull v) { return __uint_as_float((uint32_t)(v >> 32)); }

// ---------------- zero scratch -------------------------------------------------
__global__ void zero_kernel() {
    int idx = blockIdx.x * blockDim.x + threadIdx.x;
    int stride = gridDim.x * blockDim.x;
    for (int i = idx; i < NN; i += stride) g_hist[i] = 0;
    for (int i = idx; i < GG * HID; i += stride) g_pool[i] = 0.f;
    for (int i = idx; i < GG; i += stride) g_cnt[i] = 0.f;
}

// ---------------- histogram of dst ---------------------------------------------
__global__ void hist_kernel(const int* __restrict__ edge_index) {
    int e = blockIdx.x * blockDim.x + threadIdx.x;
    if (e < EE) atomicAdd(&g_hist[edge_index[EE + e]], 1);
}

// ---------------- single-block exclusive scan (warp-based) ---------------------
__global__ void scan_kernel() {
    __shared__ int warp_sums[32];
    __shared__ int carry_s;
    int t = threadIdx.x, lane = t & 31, wid = t >> 5;
    if (t == 0) carry_s = 0;
    __syncthreads();
    for (int base = 0; base < NN; base += 1024) {
        int i = base + t;
        int v = (i < NN) ? g_hist[i] : 0;
        int x = v;
        #pragma unroll
        for (int o = 1; o < 32; o <<= 1) {
            int y = __shfl_up_sync(0xffffffffu, x, o);
            if (lane >= o) x += y;
        }
        if (lane == 31) warp_sums[wid] = x;
        __syncthreads();
        if (wid == 0) {
            int w = warp_sums[lane];
            int xw = w;
            #pragma unroll
            for (int o = 1; o < 32; o <<= 1) {
                int y = __shfl_up_sync(0xffffffffu, xw, o);
                if (lane >= o) xw += y;
            }
            warp_sums[lane] = xw - w;
        }
        __syncthreads();
        int incl = x + warp_sums[wid];
        int excl = incl - v;
        int cc = carry_s;
        if (i < NN) { g_off[i] = cc + excl; g_cur[i] = cc + excl; }
        __syncthreads();
        if (t == 1023) carry_s = cc + incl;
        __syncthreads();
    }
    if (threadIdx.x == 0) g_off[NN] = carry_s;
}

// ---------------- scatter edges into CSR + edge-attr projection ---------------
__global__ void scatter_kernel(const int* __restrict__ edge_index,
                               const float* __restrict__ edge_attr,
                               const float* __restrict__ W_et, const float* __restrict__ b_et,
                               const float* __restrict__ W_uw, const float* __restrict__ b_uw,
                               const float* __restrict__ W_ua, const float* __restrict__ b_ua) {
    int e = blockIdx.x * blockDim.x + threadIdx.x;
    if (e >= EE) return;
    int s = edge_index[e];
    int d = edge_index[EE + e];
    int pos = atomicAdd(&g_cur[d], 1);
    g_csr_src[pos] = s;
    float et = edge_attr[2 * e];
    float uw = edge_attr[2 * e + 1];
    float ua = 1.f / (1.f + __expf(-(uw * W_ua[0] + b_ua[0])));
    float4 ep;
    ep.x = et * W_et[0] + b_et[0];
    ep.y = et * W_et[1] + b_et[1];
    ep.z = (uw * W_uw[0] + b_uw[0]) * ua;
    ep.w = (uw * W_uw[1] + b_uw[1]) * ua;
    g_csr_eap[pos] = ep;
}

// ---------------- FFMA2 xl/xr GEMM: [N,K] @ [K,256] (x2) + bias -----------------
template <int K, bool USE_GH>
__global__ __launch_bounds__(256) void gemm_f2_kernel(
        const float* __restrict__ x,
        const float* __restrict__ Wl, const float* __restrict__ bl,
        const float* __restrict__ Wr, const float* __restrict__ br) {
    __shared__ float xsT[K * 20];
    int t = threadIdx.x;
    int node0 = blockIdx.x * 16;
    const float* __restrict__ src = USE_GH ? (const float*)g_h : x;
    for (int i = t; i < 16 * K; i += 256) {
        int n = i / K, k = i % K;
        xsT[k * 20 + n] = src[(size_t)(node0 + n) * K + k];
    }
    __syncthreads();

    ull accl[8], accr[8];
    #pragma unroll
    for (int p = 0; p < 8; p++) { accl[p] = 0ull; accr[p] = 0ull; }

    #pragma unroll 2
    for (int k = 0; k < K; k++) {
        const ulonglong2* rp = (const ulonglong2*)(xsT + k * 20);
        ulonglong2 q0 = rp[0], q1 = rp[1], q2 = rp[2], q3 = rp[3];
        float wl = __ldg(&Wl[k * CH256 + t]);
        float wr = __ldg(&Wr[k * CH256 + t]);
        ull wld, wrd;
        DUP2(wld, wl); DUP2(wrd, wr);
        FFMA2(accl[0], q0.x, wld); FFMA2(accl[1], q0.y, wld);
        FFMA2(accl[2], q1.x, wld); FFMA2(accl[3], q1.y, wld);
        FFMA2(accl[4], q2.x, wld); FFMA2(accl[5], q2.y, wld);
        FFMA2(accl[6], q3.x, wld); FFMA2(accl[7], q3.y, wld);
        FFMA2(accr[0], q0.x, wrd); FFMA2(accr[1], q0.y, wrd);
        FFMA2(accr[2], q1.x, wrd); FFMA2(accr[3], q1.y, wrd);
        FFMA2(accr[4], q2.x, wrd); FFMA2(accr[5], q2.y, wrd);
        FFMA2(accr[6], q3.x, wrd); FFMA2(accr[7], q3.y, wrd);
    }

    float bbl = bl[t], bbr = br[t];
    #pragma unroll
    for (int p = 0; p < 8; p++) {
        size_t n = node0 + 2 * p;
        g_xl[n * CH256 + t]       = f2lo(accl[p]) + bbl;
        g_xl[(n + 1) * CH256 + t] = f2hi(accl[p]) + bbl;
        g_xr[n * CH256 + t]       = f2lo(accr[p]) + bbr;
        g_xr[(n + 1) * CH256 + t] = f2hi(accr[p]) + bbr;
    }
}

// ---------------- warp-per-edge GATv2 edge stage --------------------------------
// 256 threads = 8 warps; warp w processes edges e0+w, e0+w+8, ... of each node.
// Lane owns channels 8*lane..8*lane+7 (one head spans 8 lanes -> 3-shuffle oct
// reduce for the score). Per-warp partials combined via smem per node.
__global__ __launch_bounds__(256) void edge_kernel(
        const float* __restrict__ att, const float* __restrict__ We,
        const float* __restrict__ bias) {
    int t = threadIdx.x;
    int w = t >> 5, lane = t & 31;
    int cb = 8 * lane;                 // first owned channel

    // per-lane constants: We rows (4x8), att (8)
    float we0[8], we1[8], we2[8], we3[8], av[8];
    {
        float4 p, q;
        p = *(const float4*)(We + 0 * CH256 + cb); q = *(const float4*)(We + 0 * CH256 + cb + 4);
        we0[0]=p.x; we0[1]=p.y; we0[2]=p.z; we0[3]=p.w; we0[4]=q.x; we0[5]=q.y; we0[6]=q.z; we0[7]=q.w;
        p = *(const float4*)(We + 1 * CH256 + cb); q = *(const float4*)(We + 1 * CH256 + cb + 4);
        we1[0]=p.x; we1[1]=p.y; we1[2]=p.z; we1[3]=p.w; we1[4]=q.x; we1[5]=q.y; we1[6]=q.z; we1[7]=q.w;
        p = *(const float4*)(We + 2 * CH256 + cb); q = *(const float4*)(We + 2 * CH256 + cb + 4);
        we2[0]=p.x; we2[1]=p.y; we2[2]=p.z; we2[3]=p.w; we2[4]=q.x; we2[5]=q.y; we2[6]=q.z; we2[7]=q.w;
        p = *(const float4*)(We + 3 * CH256 + cb); q = *(const float4*)(We + 3 * CH256 + cb + 4);
        we3[0]=p.x; we3[1]=p.y; we3[2]=p.z; we3[3]=p.w; we3[4]=q.x; we3[5]=q.y; we3[6]=q.z; we3[7]=q.w;
        p = *(const float4*)(att + cb); q = *(const float4*)(att + cb + 4);
        av[0]=p.x; av[1]=p.y; av[2]=p.z; av[3]=p.w; av[4]=q.x; av[5]=q.y; av[6]=q.z; av[7]=q.w;
    }
    float bv = (t < HID) ? bias[t] : 0.f;

    __shared__ float s_acc[8][CH256];   // 8 KB
    __shared__ float s_den[8][NHEAD];

    int nbase = blockIdx.x * NPB_EDGE;
    #pragma unroll 1
    for (int ni = 0; ni < NPB_EDGE; ni++) {
        int n = nbase + ni;
        if (n >= NN) break;
        // xr row slice + fold into one register set
        float xr8[8];
        {
            const float* xp = g_xr + (size_t)n * CH256 + cb;
            float4 p = *(const float4*)xp, q = *(const float4*)(xp + 4);
            xr8[0]=p.x; xr8[1]=p.y; xr8[2]=p.z; xr8[3]=p.w; xr8[4]=q.x; xr8[5]=q.y; xr8[6]=q.z; xr8[7]=q.w;
        }
        float acc[8];
        #pragma unroll
        for (int j = 0; j < 8; j++) acc[j] = 0.f;
        float den = 0.f;
        int e0 = g_off[n], e1 = g_off[n + 1];
        for (int e = e0 + w; e < e1; e += 8) {
            int s = __ldg(&g_csr_src[e]);
            float4 ep = g_csr_eap[e];
            const float* xlp = g_xl + (size_t)s * CH256 + cb;
            float4 x0 = *(const float4*)xlp, x1 = *(const float4*)(xlp + 4);
            float xl8[8] = {x0.x, x0.y, x0.z, x0.w, x1.x, x1.y, x1.z, x1.w};
            float p = 0.f;
            #pragma unroll
            for (int j = 0; j < 8; j++) {
                float ee = fmaf(ep.x, we0[j], fmaf(ep.y, we1[j], fmaf(ep.z, we2[j], ep.w * we3[j])));
                float m = xl8[j] + xr8[j] + ee;
                m = (m > 0.f) ? m : 0.2f * m;
                p = fmaf(m, av[j], p);
            }
            // oct reduce (head = lane>>3 spans lanes 8h..8h+7)
            p += __shfl_xor_sync(0xffffffffu, p, 1);
            p += __shfl_xor_sync(0xffffffffu, p, 2);
            p += __shfl_xor_sync(0xffffffffu, p, 4);
            float ex = __expf(p);
            den += ex;
            #pragma unroll
            for (int j = 0; j < 8; j++) acc[j] = fmaf(xl8[j], ex, acc[j]);
        }
        // publish per-warp partials
        *(float4*)&s_acc[w][cb]     = make_float4(acc[0], acc[1], acc[2], acc[3]);
        *(float4*)&s_acc[w][cb + 4] = make_float4(acc[4], acc[5], acc[6], acc[7]);
        if ((lane & 7) == 0) s_den[w][lane >> 3] = den;
        __syncthreads();
        if (t < HID) {
            float v = 0.f;
            #pragma unroll
            for (int h = 0; h < NHEAD; h++) {
                float a = 0.f, d = 0.f;
                #pragma unroll
                for (int ww = 0; ww < 8; ww++) {
                    a += s_acc[ww][h * 64 + t];
                    d += s_den[ww][h];
                }
                v += a / (d + 1e-16f);
            }
            v = v * 0.25f + bv;
            g_h[n * HID + t] = (v > 0.f) ? v : 0.f;
        }
        __syncthreads();
    }
}

// ---------------- graph pooling -------------------------------------------------
__global__ void pool_kernel(const int* __restrict__ batch) {
    int idx = blockIdx.x * blockDim.x + threadIdx.x;
    if (idx >= NN * HID) return;
    int n = idx >> 6, c = idx & 63;
    int g = batch[n];
    atomicAdd(&g_pool[g * HID + c], g_h[idx]);
    if (c == 0) atomicAdd(&g_cnt[g], 1.f);
}

// ---------------- head ----------------------------------------------------------
__global__ __launch_bounds__(64) void final_kernel(
        const float* __restrict__ W_fc, const float* __restrict__ b_fc,
        const float* __restrict__ W_res, const float* __restrict__ b_res,
        const float* __restrict__ W_time, const float* __restrict__ b_time,
        float* __restrict__ out) {
    int g = blockIdx.x;
    int c = threadIdx.x;
    float inv = 1.f / fmaxf(g_cnt[g], 1.f);
    float acc = b_fc[c];
    for (int k = 0; k < HID; k++)
        acc = fmaf(g_pool[g * HID + k] * inv, W_fc[k * HID + c], acc);
    float gv = (acc > 0.f) ? acc : 0.f;
    float r  = gv * W_res[c];
    float tm = gv * W_time[c];
    #pragma unroll
    for (int o = 16; o; o >>= 1) {
        r  += __shfl_xor_sync(0xffffffffu, r, o);
        tm += __shfl_xor_sync(0xffffffffu, tm, o);
    }
    __shared__ float sr[2], st[2];
    if ((c & 31) == 0) { sr[c >> 5] = r; st[c >> 5] = tm; }
    __syncthreads();
    if (c == 0) {
        out[g * 2 + 0] = sr[0] + sr[1] + b_res[0];
        out[g * 2 + 1] = st[0] + st[1] + b_time[0];
    }
}

// ---------------- launcher -------------------------------------------------------
extern "C" void kernel_launch(void* const* d_in, const int* in_sizes, int n_in,
                              void* d_out, int out_size) {
    int I_x, I_ea, I_ei, I_b, I_Wet, I_bet, I_Wuw, I_buw, I_Wua, I_bua;
    int I_Wl0, I_bl0, I_Wr0, I_br0, I_att0, I_We0, I_bias0;
    int I_Wl1, I_bl1, I_Wr1, I_br1, I_att1, I_We1, I_bias1;
    int I_Wfc, I_bfc, I_Wres, I_bres, I_Wtime, I_btime;
    if (in_sizes[0] == 2) {
        I_Wet = 0; I_Wfc = 1; I_Wres = 2; I_Wtime = 3; I_Wua = 4; I_Wuw = 5;
        I_We0 = 6; I_We1 = 7; I_Wl0 = 8; I_Wl1 = 9; I_Wr0 = 10; I_Wr1 = 11;
        I_att0 = 12; I_att1 = 13;
        I_bet = 14; I_bfc = 15; I_bres = 16; I_btime = 17; I_bua = 18; I_buw = 19;
        I_b = 20; I_bias0 = 21; I_bias1 = 22;
        I_bl0 = 23; I_bl1 = 24; I_br0 = 25; I_br1 = 26;
        I_ea = 27; I_ei = 28; I_x = 29;
    } else if (in_sizes[2] == 2 * EE) {
        I_x = 0; I_ea = 1; I_ei = 2; I_b = 3;
        I_Wet = 4; I_bet = 5; I_Wuw = 6; I_buw = 7; I_Wua = 8; I_bua = 9;
        I_Wl0 = 10; I_bl0 = 11; I_Wr0 = 12; I_br0 = 13; I_att0 = 14; I_We0 = 15; I_bias0 = 16;
        I_Wl1 = 17; I_bl1 = 18; I_Wr1 = 19; I_br1 = 20; I_att1 = 21; I_We1 = 22; I_bias1 = 23;
        I_Wfc = 24; I_bfc = 25; I_Wres = 26; I_bres = 27; I_Wtime = 28; I_btime = 29;
    } else {
        I_x = 0; I_ea = 1;
        I_Wet = 2; I_bet = 3; I_Wuw = 4; I_buw = 5; I_Wua = 6; I_bua = 7;
        I_Wl0 = 8; I_bl0 = 9; I_Wr0 = 10; I_br0 = 11; I_att0 = 12; I_We0 = 13; I_bias0 = 14;
        I_Wl1 = 15; I_bl1 = 16; I_Wr1 = 17; I_br1 = 18; I_att1 = 19; I_We1 = 20; I_bias1 = 21;
        I_Wfc = 22; I_bfc = 23; I_Wres = 24; I_bres = 25; I_Wtime = 26; I_btime = 27;
        I_ei = 28; I_b = 29;
    }

    const float* x        = (const float*)d_in[I_x];
    const float* edge_attr= (const float*)d_in[I_ea];
    const int*   edge_idx = (const int*)  d_in[I_ei];
    const int*   batch    = (const int*)  d_in[I_b];
    const float* W_et = (const float*)d_in[I_Wet], *b_et = (const float*)d_in[I_bet];
    const float* W_uw = (const float*)d_in[I_Wuw], *b_uw = (const float*)d_in[I_buw];
    const float* W_ua = (const float*)d_in[I_Wua], *b_ua = (const float*)d_in[I_bua];
    const float* Wl0 = (const float*)d_in[I_Wl0], *bl0 = (const float*)d_in[I_bl0];
    const float* Wr0 = (const float*)d_in[I_Wr0], *br0 = (const float*)d_in[I_br0];
    const float* att0 = (const float*)d_in[I_att0], *We0 = (const float*)d_in[I_We0];
    const float* bias0 = (const float*)d_in[I_bias0];
    const float* Wl1 = (const float*)d_in[I_Wl1], *bl1 = (const float*)d_in[I_bl1];
    const float* Wr1 = (const float*)d_in[I_Wr1], *br1 = (const float*)d_in[I_br1];
    const float* att1 = (const float*)d_in[I_att1], *We1 = (const float*)d_in[I_We1];
    const float* bias1 = (const float*)d_in[I_bias1];
    const float* W_fc = (const float*)d_in[I_Wfc], *b_fc = (const float*)d_in[I_bfc];
    const float* W_res = (const float*)d_in[I_Wres], *b_res = (const float*)d_in[I_bres];
    const float* W_time = (const float*)d_in[I_Wtime], *b_time = (const float*)d_in[I_btime];
    float* out = (float*)d_out;

    // launch order: position 4 is the ncu-profiled launch -> layer-0 GEMM.
    zero_kernel<<<128, 256>>>();                                   // 1
    hist_kernel<<<(EE + 255) / 256, 256>>>(edge_idx);              // 2
    scan_kernel<<<1, 1024>>>();                                    // 3
    gemm_f2_kernel<IN_CH, false><<<NN / 16, 256>>>(                // 4  <- profiled
        x, Wl0, bl0, Wr0, br0);
    scatter_kernel<<<(EE + 255) / 256, 256>>>(edge_idx, edge_attr, // 5
                                              W_et, b_et, W_uw, b_uw, W_ua, b_ua);
    edge_kernel<<<(NN + NPB_EDGE - 1) / NPB_EDGE, 256>>>(att0, We0, bias0);  // 6
    gemm_f2_kernel<HID, true><<<NN / 16, 256>>>(                   // 7
        nullptr, Wl1, bl1, Wr1, br1);
    edge_kernel<<<(NN + NPB_EDGE - 1) / NPB_EDGE, 256>>>(att1, We1, bias1);  // 8
    pool_kernel<<<(NN * HID + 255) / 256, 256>>>(batch);           // 9
    final_kernel<<<GG, 64>>>(W_fc, b_fc, W_res, b_res, W_time, b_time, out); // 10
}

// round 10
// speedup vs baseline: 1.5562x; 1.5562x over previous
#include <cuda_runtime.h>
#include <cuda_bf16.h>
#include <cstdint>
#include <math.h>

// Problem constants
#define NN 50000
#define EE 400000
#define GG 64
#define IN_CH 128
#define HID 64
#define NHEAD 4
#define CH256 256   // NHEAD*HID

typedef unsigned long long ull;

// ---------------- scratch (static __device__ globals; no allocation) ----------
__device__ float  g_xl[NN * CH256];     // 51.2 MB
__device__ float  g_xr[NN * CH256];     // 51.2 MB
__device__ float  g_h [NN * HID];       // 12.8 MB
__device__ int    g_hist[NN];
__device__ int    g_off [NN + 1];
__device__ int    g_cur [NN];
__device__ int    g_csr_src[EE];
__device__ float4 g_csr_eap[EE];
__device__ float  g_pool[GG * HID];
__device__ float  g_cnt [GG];

// ---------------- packed f32x2 helpers ------------------------------------------
#define FFMA2(d, a, b) \
    asm("fma.rn.f32x2 %0, %1, %2, %0;" : "+l"(d) : "l"(a), "l"(b))
#define DUP2(d, f) \
    asm("mov.b64 %0, {%1, %1};" : "=l"(d) : "f"(f))
__device__ __forceinline__ float f2lo(ull v) { return __uint_as_float((uint32_t)v); }
__device__ __forceinline__ float f2hi(ull v) { return __uint_as_float((uint32_t)(v >> 32)); }

// ---------------- zero scratch -------------------------------------------------
__global__ void zero_kernel() {
    int idx = blockIdx.x * blockDim.x + threadIdx.x;
    int stride = gridDim.x * blockDim.x;
    for (int i = idx; i < NN; i += stride) g_hist[i] = 0;
    for (int i = idx; i < GG * HID; i += stride) g_pool[i] = 0.f;
    for (int i = idx; i < GG; i += stride) g_cnt[i] = 0.f;
}

// ---------------- histogram of dst ---------------------------------------------
__global__ void hist_kernel(const int* __restrict__ edge_index) {
    int e = blockIdx.x * blockDim.x + threadIdx.x;
    if (e < EE) atomicAdd(&g_hist[edge_index[EE + e]], 1);
}

// ---------------- single-block exclusive scan (warp-based) ---------------------
__global__ void scan_kernel() {
    __shared__ int warp_sums[32];
    __shared__ int carry_s;
    int t = threadIdx.x, lane = t & 31, wid = t >> 5;
    if (t == 0) carry_s = 0;
    __syncthreads();
    for (int base = 0; base < NN; base += 1024) {
        int i = base + t;
        int v = (i < NN) ? g_hist[i] : 0;
        int x = v;
        #pragma unroll
        for (int o = 1; o < 32; o <<= 1) {
            int y = __shfl_up_sync(0xffffffffu, x, o);
            if (lane >= o) x += y;
        }
        if (lane == 31) warp_sums[wid] = x;
        __syncthreads();
        if (wid == 0) {
            int w = warp_sums[lane];
            int xw = w;
            #pragma unroll
            for (int o = 1; o < 32; o <<= 1) {
                int y = __shfl_up_sync(0xffffffffu, xw, o);
                if (lane >= o) xw += y;
            }
            warp_sums[lane] = xw - w;
        }
        __syncthreads();
        int incl = x + warp_sums[wid];
        int excl = incl - v;
        int cc = carry_s;
        if (i < NN) { g_off[i] = cc + excl; g_cur[i] = cc + excl; }
        __syncthreads();
        if (t == 1023) carry_s = cc + incl;
        __syncthreads();
    }
    if (threadIdx.x == 0) g_off[NN] = carry_s;
}

// ---------------- scatter edges into CSR + edge-attr projection ---------------
__global__ void scatter_kernel(const int* __restrict__ edge_index,
                               const float* __restrict__ edge_attr,
                               const float* __restrict__ W_et, const float* __restrict__ b_et,
                               const float* __restrict__ W_uw, const float* __restrict__ b_uw,
                               const float* __restrict__ W_ua, const float* __restrict__ b_ua) {
    int e = blockIdx.x * blockDim.x + threadIdx.x;
    if (e >= EE) return;
    int s = edge_index[e];
    int d = edge_index[EE + e];
    int pos = atomicAdd(&g_cur[d], 1);
    g_csr_src[pos] = s;
    float et = edge_attr[2 * e];
    float uw = edge_attr[2 * e + 1];
    float ua = 1.f / (1.f + __expf(-(uw * W_ua[0] + b_ua[0])));
    float4 ep;
    ep.x = et * W_et[0] + b_et[0];
    ep.y = et * W_et[1] + b_et[1];
    ep.z = (uw * W_uw[0] + b_uw[0]) * ua;
    ep.w = (uw * W_uw[1] + b_uw[1]) * ua;
    g_csr_eap[pos] = ep;
}

// ---------------- FFMA2 xl/xr GEMM: [N,K] @ [K,256] (x2) + bias -----------------
template <int K, bool USE_GH>
__global__ __launch_bounds__(256) void gemm_f2_kernel(
        const float* __restrict__ x,
        const float* __restrict__ Wl, const float* __restrict__ bl,
        const float* __restrict__ Wr, const float* __restrict__ br) {
    __shared__ float xsT[K * 20];
    int t = threadIdx.x;
    int node0 = blockIdx.x * 16;
    const float* __restrict__ src = USE_GH ? (const float*)g_h : x;
    for (int i = t; i < 16 * K; i += 256) {
        int n = i / K, k = i % K;
        xsT[k * 20 + n] = src[(size_t)(node0 + n) * K + k];
    }
    __syncthreads();

    ull accl[8], accr[8];
    #pragma unroll
    for (int p = 0; p < 8; p++) { accl[p] = 0ull; accr[p] = 0ull; }

    #pragma unroll 2
    for (int k = 0; k < K; k++) {
        const ulonglong2* rp = (const ulonglong2*)(xsT + k * 20);
        ulonglong2 q0 = rp[0], q1 = rp[1], q2 = rp[2], q3 = rp[3];
        float wl = __ldg(&Wl[k * CH256 + t]);
        float wr = __ldg(&Wr[k * CH256 + t]);
        ull wld, wrd;
        DUP2(wld, wl); DUP2(wrd, wr);
        FFMA2(accl[0], q0.x, wld); FFMA2(accl[1], q0.y, wld);
        FFMA2(accl[2], q1.x, wld); FFMA2(accl[3], q1.y, wld);
        FFMA2(accl[4], q2.x, wld); FFMA2(accl[5], q2.y, wld);
        FFMA2(accl[6], q3.x, wld); FFMA2(accl[7], q3.y, wld);
        FFMA2(accr[0], q0.x, wrd); FFMA2(accr[1], q0.y, wrd);
        FFMA2(accr[2], q1.x, wrd); FFMA2(accr[3], q1.y, wrd);
        FFMA2(accr[4], q2.x, wrd); FFMA2(accr[5], q2.y, wrd);
        FFMA2(accr[6], q3.x, wrd); FFMA2(accr[7], q3.y, wrd);
    }

    float bbl = bl[t], bbr = br[t];
    #pragma unroll
    for (int p = 0; p < 8; p++) {
        size_t n = node0 + 2 * p;
        g_xl[n * CH256 + t]       = f2lo(accl[p]) + bbl;
        g_xl[(n + 1) * CH256 + t] = f2hi(accl[p]) + bbl;
        g_xr[n * CH256 + t]       = f2lo(accr[p]) + bbr;
        g_xr[(n + 1) * CH256 + t] = f2hi(accr[p]) + bbr;
    }
}

// ---------------- warp-per-node GATv2 edge stage ---------------------------------
// 8 warps per block, each warp owns ONE dst node end-to-end: no smem, no
// __syncthreads. Lane owns channels 8*lane..8*lane+7; a head spans one lane
// octet (3-shuffle score reduce); the head-mean is 2 more shuffles (xor 8/16),
// leaving lanes 0..7 holding output channels 8l..8l+7 (two float4 stores).
__global__ __launch_bounds__(256) void edge_kernel(
        const float* __restrict__ att, const float* __restrict__ We,
        const float* __restrict__ bias) {
    int t = threadIdx.x;
    int w = t >> 5, lane = t & 31;
    int cb = 8 * lane;                 // first owned channel
    int n = blockIdx.x * 8 + w;
    if (n >= NN) return;

    // per-lane constants: We rows (4x8), att (8) — coalesced float4 loads
    float we0[8], we1[8], we2[8], we3[8], av[8];
    {
        float4 p, q;
        p = *(const float4*)(We + 0 * CH256 + cb); q = *(const float4*)(We + 0 * CH256 + cb + 4);
        we0[0]=p.x; we0[1]=p.y; we0[2]=p.z; we0[3]=p.w; we0[4]=q.x; we0[5]=q.y; we0[6]=q.z; we0[7]=q.w;
        p = *(const float4*)(We + 1 * CH256 + cb); q = *(const float4*)(We + 1 * CH256 + cb + 4);
        we1[0]=p.x; we1[1]=p.y; we1[2]=p.z; we1[3]=p.w; we1[4]=q.x; we1[5]=q.y; we1[6]=q.z; we1[7]=q.w;
        p = *(const float4*)(We + 2 * CH256 + cb); q = *(const float4*)(We + 2 * CH256 + cb + 4);
        we2[0]=p.x; we2[1]=p.y; we2[2]=p.z; we2[3]=p.w; we2[4]=q.x; we2[5]=q.y; we2[6]=q.z; we2[7]=q.w;
        p = *(const float4*)(We + 3 * CH256 + cb); q = *(const float4*)(We + 3 * CH256 + cb + 4);
        we3[0]=p.x; we3[1]=p.y; we3[2]=p.z; we3[3]=p.w; we3[4]=q.x; we3[5]=q.y; we3[6]=q.z; we3[7]=q.w;
        p = *(const float4*)(att + cb); q = *(const float4*)(att + cb + 4);
        av[0]=p.x; av[1]=p.y; av[2]=p.z; av[3]=p.w; av[4]=q.x; av[5]=q.y; av[6]=q.z; av[7]=q.w;
    }

    float xr8[8];
    {
        const float* xp = g_xr + (size_t)n * CH256 + cb;
        float4 p = *(const float4*)xp, q = *(const float4*)(xp + 4);
        xr8[0]=p.x; xr8[1]=p.y; xr8[2]=p.z; xr8[3]=p.w; xr8[4]=q.x; xr8[5]=q.y; xr8[6]=q.z; xr8[7]=q.w;
    }

    float acc[8];
    #pragma unroll
    for (int j = 0; j < 8; j++) acc[j] = 0.f;
    float den = 0.f;
    int e0 = g_off[n], e1 = g_off[n + 1];
    #pragma unroll 2
    for (int e = e0; e < e1; e++) {
        int s = __ldg(&g_csr_src[e]);         // warp-uniform broadcast
        float4 ep = g_csr_eap[e];             // warp-uniform broadcast
        const float* xlp = g_xl + (size_t)s * CH256 + cb;
        float4 x0 = *(const float4*)xlp, x1 = *(const float4*)(xlp + 4);
        float xl8[8] = {x0.x, x0.y, x0.z, x0.w, x1.x, x1.y, x1.z, x1.w};
        float p = 0.f;
        #pragma unroll
        for (int j = 0; j < 8; j++) {
            float ee = fmaf(ep.x, we0[j], fmaf(ep.y, we1[j], fmaf(ep.z, we2[j], ep.w * we3[j])));
            float m = xl8[j] + xr8[j] + ee;
            m = (m > 0.f) ? m : 0.2f * m;
            p = fmaf(m, av[j], p);
        }
        // oct reduce within the head's lane octet
        p += __shfl_xor_sync(0xffffffffu, p, 1);
        p += __shfl_xor_sync(0xffffffffu, p, 2);
        p += __shfl_xor_sync(0xffffffffu, p, 4);
        float ex = __expf(p);
        den += ex;
        #pragma unroll
        for (int j = 0; j < 8; j++) acc[j] = fmaf(xl8[j], ex, acc[j]);
    }
    // normalize by own head's denominator, then sum the 4 heads (lanes xor 8/16)
    float inv = 1.f / (den + 1e-16f);
    #pragma unroll
    for (int j = 0; j < 8; j++) {
        float v = acc[j] * inv;
        v += __shfl_xor_sync(0xffffffffu, v, 8);
        v += __shfl_xor_sync(0xffffffffu, v, 16);
        acc[j] = v;
    }
    if (lane < 8) {
        float4 b0 = *(const float4*)(bias + 8 * lane);
        float4 b1 = *(const float4*)(bias + 8 * lane + 4);
        float o0 = fmaxf(acc[0] * 0.25f + b0.x, 0.f);
        float o1 = fmaxf(acc[1] * 0.25f + b0.y, 0.f);
        float o2 = fmaxf(acc[2] * 0.25f + b0.z, 0.f);
        float o3 = fmaxf(acc[3] * 0.25f + b0.w, 0.f);
        float o4 = fmaxf(acc[4] * 0.25f + b1.x, 0.f);
        float o5 = fmaxf(acc[5] * 0.25f + b1.y, 0.f);
        float o6 = fmaxf(acc[6] * 0.25f + b1.z, 0.f);
        float o7 = fmaxf(acc[7] * 0.25f + b1.w, 0.f);
        float* hp = g_h + (size_t)n * HID + 8 * lane;
        *(float4*)hp       = make_float4(o0, o1, o2, o3);
        *(float4*)(hp + 4) = make_float4(o4, o5, o6, o7);
    }
}

// ---------------- graph pooling -------------------------------------------------
__global__ void pool_kernel(const int* __restrict__ batch) {
    int idx = blockIdx.x * blockDim.x + threadIdx.x;
    if (idx >= NN * HID) return;
    int n = idx >> 6, c = idx & 63;
    int g = batch[n];
    atomicAdd(&g_pool[g * HID + c], g_h[idx]);
    if (c == 0) atomicAdd(&g_cnt[g], 1.f);
}

// ---------------- head ----------------------------------------------------------
__global__ __launch_bounds__(64) void final_kernel(
        const float* __restrict__ W_fc, const float* __restrict__ b_fc,
        const float* __restrict__ W_res, const float* __restrict__ b_res,
        const float* __restrict__ W_time, const float* __restrict__ b_time,
        float* __restrict__ out) {
    int g = blockIdx.x;
    int c = threadIdx.x;
    float inv = 1.f / fmaxf(g_cnt[g], 1.f);
    float acc = b_fc[c];
    for (int k = 0; k < HID; k++)
        acc = fmaf(g_pool[g * HID + k] * inv, W_fc[k * HID + c], acc);
    float gv = (acc > 0.f) ? acc : 0.f;
    float r  = gv * W_res[c];
    float tm = gv * W_time[c];
    #pragma unroll
    for (int o = 16; o; o >>= 1) {
        r  += __shfl_xor_sync(0xffffffffu, r, o);
        tm += __shfl_xor_sync(0xffffffffu, tm, o);
    }
    __shared__ float sr[2], st[2];
    if ((c & 31) == 0) { sr[c >> 5] = r; st[c >> 5] = tm; }
    __syncthreads();
    if (c == 0) {
        out[g * 2 + 0] = sr[0] + sr[1] + b_res[0];
        out[g * 2 + 1] = st[0] + st[1] + b_time[0];
    }
}

// ---------------- launcher -------------------------------------------------------
extern "C" void kernel_launch(void* const* d_in, const int* in_sizes, int n_in,
                              void* d_out, int out_size) {
    int I_x, I_ea, I_ei, I_b, I_Wet, I_bet, I_Wuw, I_buw, I_Wua, I_bua;
    int I_Wl0, I_bl0, I_Wr0, I_br0, I_att0, I_We0, I_bias0;
    int I_Wl1, I_bl1, I_Wr1, I_br1, I_att1, I_We1, I_bias1;
    int I_Wfc, I_bfc, I_Wres, I_bres, I_Wtime, I_btime;
    if (in_sizes[0] == 2) {
        I_Wet = 0; I_Wfc = 1; I_Wres = 2; I_Wtime = 3; I_Wua = 4; I_Wuw = 5;
        I_We0 = 6; I_We1 = 7; I_Wl0 = 8; I_Wl1 = 9; I_Wr0 = 10; I_Wr1 = 11;
        I_att0 = 12; I_att1 = 13;
        I_bet = 14; I_bfc = 15; I_bres = 16; I_btime = 17; I_bua = 18; I_buw = 19;
        I_b = 20; I_bias0 = 21; I_bias1 = 22;
        I_bl0 = 23; I_bl1 = 24; I_br0 = 25; I_br1 = 26;
        I_ea = 27; I_ei = 28; I_x = 29;
    } else if (in_sizes[2] == 2 * EE) {
        I_x = 0; I_ea = 1; I_ei = 2; I_b = 3;
        I_Wet = 4; I_bet = 5; I_Wuw = 6; I_buw = 7; I_Wua = 8; I_bua = 9;
        I_Wl0 = 10; I_bl0 = 11; I_Wr0 = 12; I_br0 = 13; I_att0 = 14; I_We0 = 15; I_bias0 = 16;
        I_Wl1 = 17; I_bl1 = 18; I_Wr1 = 19; I_br1 = 20; I_att1 = 21; I_We1 = 22; I_bias1 = 23;
        I_Wfc = 24; I_bfc = 25; I_Wres = 26; I_bres = 27; I_Wtime = 28; I_btime = 29;
    } else {
        I_x = 0; I_ea = 1;
        I_Wet = 2; I_bet = 3; I_Wuw = 4; I_buw = 5; I_Wua = 6; I_bua = 7;
        I_Wl0 = 8; I_bl0 = 9; I_Wr0 = 10; I_br0 = 11; I_att0 = 12; I_We0 = 13; I_bias0 = 14;
        I_Wl1 = 15; I_bl1 = 16; I_Wr1 = 17; I_br1 = 18; I_att1 = 19; I_We1 = 20; I_bias1 = 21;
        I_Wfc = 22; I_bfc = 23; I_Wres = 24; I_bres = 25; I_Wtime = 26; I_btime = 27;
        I_ei = 28; I_b = 29;
    }

    const float* x        = (const float*)d_in[I_x];
    const float* edge_attr= (const float*)d_in[I_ea];
    const int*   edge_idx = (const int*)  d_in[I_ei];
    const int*   batch    = (const int*)  d_in[I_b];
    const float* W_et = (const float*)d_in[I_Wet], *b_et = (const float*)d_in[I_bet];
    const float* W_uw = (const float*)d_in[I_Wuw], *b_uw = (const float*)d_in[I_buw];
    const float* W_ua = (const float*)d_in[I_Wua], *b_ua = (const float*)d_in[I_bua];
    const float* Wl0 = (const float*)d_in[I_Wl0], *bl0 = (const float*)d_in[I_bl0];
    const float* Wr0 = (const float*)d_in[I_Wr0], *br0 = (const float*)d_in[I_br0];
    const float* att0 = (const float*)d_in[I_att0], *We0 = (const float*)d_in[I_We0];
    const float* bias0 = (const float*)d_in[I_bias0];
    const float* Wl1 = (const float*)d_in[I_Wl1], *bl1 = (const float*)d_in[I_bl1];
    const float* Wr1 = (const float*)d_in[I_Wr1], *br1 = (const float*)d_in[I_br1];
    const float* att1 = (const float*)d_in[I_att1], *We1 = (const float*)d_in[I_We1];
    const float* bias1 = (const float*)d_in[I_bias1];
    const float* W_fc = (const float*)d_in[I_Wfc], *b_fc = (const float*)d_in[I_bfc];
    const float* W_res = (const float*)d_in[I_Wres], *b_res = (const float*)d_in[I_bres];
    const float* W_time = (const float*)d_in[I_Wtime], *b_time = (const float*)d_in[I_btime];
    float* out = (float*)d_out;

    // launch order: position 4 is the ncu-profiled launch -> layer-0 GEMM.
    zero_kernel<<<128, 256>>>();                                   // 1
    hist_kernel<<<(EE + 255) / 256, 256>>>(edge_idx);              // 2
    scan_kernel<<<1, 1024>>>();                                    // 3
    gemm_f2_kernel<IN_CH, false><<<NN / 16, 256>>>(                // 4  <- profiled
        x, Wl0, bl0, Wr0, br0);
    scatter_kernel<<<(EE + 255) / 256, 256>>>(edge_idx, edge_attr, // 5
                                              W_et, b_et, W_uw, b_uw, W_ua, b_ua);
    edge_kernel<<<(NN + 7) / 8, 256>>>(att0, We0, bias0);          // 6
    gemm_f2_kernel<HID, true><<<NN / 16, 256>>>(                   // 7
        nullptr, Wl1, bl1, Wr1, br1);
    edge_kernel<<<(NN + 7) / 8, 256>>>(att1, We1, bias1);          // 8
    pool_kernel<<<(NN * HID + 255) / 256, 256>>>(batch);           // 9
    final_kernel<<<GG, 64>>>(W_fc, b_fc, W_res, b_res, W_time, b_time, out); // 10
}

// round 13
// speedup vs baseline: 1.6262x; 1.0450x over previous
#include <cuda_runtime.h>
#include <cuda_bf16.h>
#include <cstdint>
#include <math.h>

// Problem constants
#define NN 50000
#define EE 400000
#define GG 64
#define IN_CH 128
#define HID 64
#define NHEAD 4
#define CH256 256   // NHEAD*HID

typedef unsigned long long ull;

// ---------------- scratch (static __device__ globals; no allocation) ----------
// NOTE: g_hist/g_pool/g_cnt are zero at module load and re-zeroed by
// cleanup_kernel at the END of every kernel_launch, so every replay
// (including the first) sees identical initial state.
// All arrays touched by >=16B vector accesses carry explicit 16B alignment.
__device__ __align__(16) float  g_xl[NN * CH256];     // 51.2 MB
__device__ __align__(16) float  g_xr[NN * CH256];     // 51.2 MB
__device__ __align__(16) float  g_h [NN * HID];       // 12.8 MB
__device__ __align__(16) int    g_hist[NN];
__device__ __align__(16) int    g_off [NN + 4];
__device__ __align__(16) int    g_cur [NN + 4];
__device__ __align__(16) int    g_csr_src[EE];
__device__ __align__(16) float4 g_csr_eap[EE];
__device__ __align__(16) float  g_pool[GG * HID];
__device__ __align__(16) float  g_cnt [GG];

// ---------------- packed f32x2 helpers ------------------------------------------
#define FFMA2(d, a, b) \
    asm("fma.rn.f32x2 %0, %1, %2, %0;" : "+l"(d) : "l"(a), "l"(b))
#define DUP2(d, f) \
    asm("mov.b64 %0, {%1, %1};" : "=l"(d) : "f"(f))
__device__ __forceinline__ float f2lo(ull v) { return __uint_as_float((uint32_t)v); }
__device__ __forceinline__ float f2hi(ull v) { return __uint_as_float((uint32_t)(v >> 32)); }

// ---------------- histogram of dst ---------------------------------------------
__global__ void hist_kernel(const int* __restrict__ edge_index) {
    int e = blockIdx.x * blockDim.x + threadIdx.x;
    if (e < EE) atomicAdd(&g_hist[edge_index[EE + e]], 1);
}

// ---------------- 256-thread block scan (8 values/thread, ~25 iterations) -------
__device__ void scan_block256() {
    __shared__ __align__(16) int wsum[8];
    __shared__ int s_carry;
    int t = threadIdx.x, lane = t & 31, wid = t >> 5;
    if (t == 0) s_carry = 0;
    __syncthreads();
    for (int base = 0; base < NN; base += 2048) {
        int i0 = base + t * 8;
        int v[8];
        if (i0 + 8 <= NN) {
            int4 a = *(const int4*)(g_hist + i0);
            int4 b = *(const int4*)(g_hist + i0 + 4);
            v[0]=a.x; v[1]=a.y; v[2]=a.z; v[3]=a.w;
            v[4]=b.x; v[5]=b.y; v[6]=b.z; v[7]=b.w;
        } else {
            #pragma unroll
            for (int j = 0; j < 8; j++) v[j] = (i0 + j < NN) ? g_hist[i0 + j] : 0;
        }
        int pre[8]; int s = 0;
        #pragma unroll
        for (int j = 0; j < 8; j++) { pre[j] = s; s += v[j]; }
        int x = s;
        #pragma unroll
        for (int o = 1; o < 32; o <<= 1) {
            int y = __shfl_up_sync(0xffffffffu, x, o);
            if (lane >= o) x += y;
        }
        if (lane == 31) wsum[wid] = x;
        __syncthreads();
        if (t == 0) {
            int c = s_carry;
            #pragma unroll
            for (int w8 = 0; w8 < 8; w8++) { int tmp = wsum[w8]; wsum[w8] = c; c += tmp; }
            s_carry = c;
        }
        __syncthreads();
        int toff = wsum[wid] + (x - s);   // exclusive offset of this thread
        #pragma unroll
        for (int j = 0; j < 8; j++) {
            int i = i0 + j;
            if (i < NN) { int e = toff + pre[j]; g_off[i] = e; g_cur[i] = e; }
        }
        __syncthreads();
    }
    if (t == 0) g_off[NN] = s_carry;
}

// ---------------- FFMA2 GEMM body ------------------------------------------------
template <int K, bool USE_GH>
__device__ __forceinline__ void gemm_body(int bx,
        const float* __restrict__ x,
        const float* __restrict__ Wl, const float* __restrict__ bl,
        const float* __restrict__ Wr, const float* __restrict__ br,
        float* xsT) {
    int t = threadIdx.x;
    int node0 = bx * 16;
    const float* __restrict__ src = USE_GH ? (const float*)g_h : x;
    for (int i = t; i < 16 * K; i += 256) {
        int n = i / K, k = i % K;
        xsT[k * 20 + n] = src[(size_t)(node0 + n) * K + k];
    }
    __syncthreads();

    ull accl[8], accr[8];
    #pragma unroll
    for (int p = 0; p < 8; p++) { accl[p] = 0ull; accr[p] = 0ull; }

    #pragma unroll 2
    for (int k = 0; k < K; k++) {
        const ulonglong2* rp = (const ulonglong2*)(xsT + k * 20);
        ulonglong2 q0 = rp[0], q1 = rp[1], q2 = rp[2], q3 = rp[3];
        float wl = __ldg(&Wl[k * CH256 + t]);
        float wr = __ldg(&Wr[k * CH256 + t]);
        ull wld, wrd;
        DUP2(wld, wl); DUP2(wrd, wr);
        FFMA2(accl[0], q0.x, wld); FFMA2(accl[1], q0.y, wld);
        FFMA2(accl[2], q1.x, wld); FFMA2(accl[3], q1.y, wld);
        FFMA2(accl[4], q2.x, wld); FFMA2(accl[5], q2.y, wld);
        FFMA2(accl[6], q3.x, wld); FFMA2(accl[7], q3.y, wld);
        FFMA2(accr[0], q0.x, wrd); FFMA2(accr[1], q0.y, wrd);
        FFMA2(accr[2], q1.x, wrd); FFMA2(accr[3], q1.y, wrd);
        FFMA2(accr[4], q2.x, wrd); FFMA2(accr[5], q2.y, wrd);
        FFMA2(accr[6], q3.x, wrd); FFMA2(accr[7], q3.y, wrd);
    }

    float bbl = bl[t], bbr = br[t];
    #pragma unroll
    for (int p = 0; p < 8; p++) {
        size_t n = node0 + 2 * p;
        g_xl[n * CH256 + t]       = f2lo(accl[p]) + bbl;
        g_xl[(n + 1) * CH256 + t] = f2hi(accl[p]) + bbl;
        g_xr[n * CH256 + t]       = f2lo(accr[p]) + bbr;
        g_xr[(n + 1) * CH256 + t] = f2hi(accr[p]) + bbr;
    }
}

// layer-0 GEMM fused with the CSR scan: block 0 scans, blocks 1.. do GEMM.
__global__ __launch_bounds__(256) void gemm_scan_kernel(
        const float* __restrict__ x,
        const float* __restrict__ Wl, const float* __restrict__ bl,
        const float* __restrict__ Wr, const float* __restrict__ br) {
    __shared__ __align__(16) float xsT[IN_CH * 20];
    if (blockIdx.x == 0) { scan_block256(); return; }
    gemm_body<IN_CH, false>(blockIdx.x - 1, x, Wl, bl, Wr, br, xsT);
}

__global__ __launch_bounds__(256) void gemm_f2_kernel1(
        const float* __restrict__ Wl, const float* __restrict__ bl,
        const float* __restrict__ Wr, const float* __restrict__ br) {
    __shared__ __align__(16) float xsT[HID * 20];
    gemm_body<HID, true>(blockIdx.x, nullptr, Wl, bl, Wr, br, xsT);
}

// ---------------- scatter edges into CSR + edge-attr projection ---------------
__global__ void scatter_kernel(const int* __restrict__ edge_index,
                               const float* __restrict__ edge_attr,
                               const float* __restrict__ W_et, const float* __restrict__ b_et,
                               const float* __restrict__ W_uw, const float* __restrict__ b_uw,
                               const float* __restrict__ W_ua, const float* __restrict__ b_ua) {
    int e = blockIdx.x * blockDim.x + threadIdx.x;
    if (e >= EE) return;
    int s = edge_index[e];
    int d = edge_index[EE + e];
    int pos = atomicAdd(&g_cur[d], 1);
    g_csr_src[pos] = s;
    float et = edge_attr[2 * e];
    float uw = edge_attr[2 * e + 1];
    float ua = 1.f / (1.f + __expf(-(uw * W_ua[0] + b_ua[0])));
    float4 ep;
    ep.x = et * W_et[0] + b_et[0];
    ep.y = et * W_et[1] + b_et[1];
    ep.z = (uw * W_uw[0] + b_uw[0]) * ua;
    ep.w = (uw * W_uw[1] + b_uw[1]) * ua;
    g_csr_eap[pos] = ep;
}

// ---------------- warp-per-node GATv2 edge stage (software-pipelined) -----------
__global__ __launch_bounds__(256) void edge_kernel(
        const float* __restrict__ att, const float* __restrict__ We,
        const float* __restrict__ bias) {
    int t = threadIdx.x;
    int w = t >> 5, lane = t & 31;
    int cb = 8 * lane;
    int n = blockIdx.x * 8 + w;
    if (n >= NN) return;

    float we0[8], we1[8], we2[8], we3[8], av[8];
    {
        float4 p, q;
        p = *(const float4*)(We + 0 * CH256 + cb); q = *(const float4*)(We + 0 * CH256 + cb + 4);
        we0[0]=p.x; we0[1]=p.y; we0[2]=p.z; we0[3]=p.w; we0[4]=q.x; we0[5]=q.y; we0[6]=q.z; we0[7]=q.w;
        p = *(const float4*)(We + 1 * CH256 + cb); q = *(const float4*)(We + 1 * CH256 + cb + 4);
        we1[0]=p.x; we1[1]=p.y; we1[2]=p.z; we1[3]=p.w; we1[4]=q.x; we1[5]=q.y; we1[6]=q.z; we1[7]=q.w;
        p = *(const float4*)(We + 2 * CH256 + cb); q = *(const float4*)(We + 2 * CH256 + cb + 4);
        we2[0]=p.x; we2[1]=p.y; we2[2]=p.z; we2[3]=p.w; we2[4]=q.x; we2[5]=q.y; we2[6]=q.z; we2[7]=q.w;
        p = *(const float4*)(We + 3 * CH256 + cb); q = *(const float4*)(We + 3 * CH256 + cb + 4);
        we3[0]=p.x; we3[1]=p.y; we3[2]=p.z; we3[3]=p.w; we3[4]=q.x; we3[5]=q.y; we3[6]=q.z; we3[7]=q.w;
        p = *(const float4*)(att + cb); q = *(const float4*)(att + cb + 4);
        av[0]=p.x; av[1]=p.y; av[2]=p.z; av[3]=p.w; av[4]=q.x; av[5]=q.y; av[6]=q.z; av[7]=q.w;
    }

    float xr8[8];
    {
        const float* xp = g_xr + (size_t)n * CH256 + cb;
        float4 p = *(const float4*)xp, q = *(const float4*)(xp + 4);
        xr8[0]=p.x; xr8[1]=p.y; xr8[2]=p.z; xr8[3]=p.w; xr8[4]=q.x; xr8[5]=q.y; xr8[6]=q.z; xr8[7]=q.w;
    }

    float acc[8];
    #pragma unroll
    for (int j = 0; j < 8; j++) acc[j] = 0.f;
    float den = 0.f;
    int e0 = g_off[n], e1 = g_off[n + 1];

    // 2-stage pipeline: (src, eap) of the NEXT edge load while the CURRENT
    // xl gather + math are in flight.
    int e = e0;
    int s_cur = 0; float4 ep_cur = make_float4(0.f, 0.f, 0.f, 0.f);
    if (e < e1) { s_cur = __ldg(&g_csr_src[e]); ep_cur = g_csr_eap[e]; }
    while (e < e1) {
        const float* xlp = g_xl + (size_t)s_cur * CH256 + cb;
        float4 x0 = *(const float4*)xlp;
        float4 x1 = *(const float4*)(xlp + 4);
        int en = e + 1;
        int s_nxt = s_cur; float4 ep_nxt = ep_cur;
        if (en < e1) { s_nxt = __ldg(&g_csr_src[en]); ep_nxt = g_csr_eap[en]; }
        float xl8[8] = {x0.x, x0.y, x0.z, x0.w, x1.x, x1.y, x1.z, x1.w};
        float p = 0.f;
        #pragma unroll
        for (int j = 0; j < 8; j++) {
            float ee = fmaf(ep_cur.x, we0[j], fmaf(ep_cur.y, we1[j],
                       fmaf(ep_cur.z, we2[j], ep_cur.w * we3[j])));
            float m = xl8[j] + xr8[j] + ee;
            m = (m > 0.f) ? m : 0.2f * m;
            p = fmaf(m, av[j], p);
        }
        p += __shfl_xor_sync(0xffffffffu, p, 1);
        p += __shfl_xor_sync(0xffffffffu, p, 2);
        p += __shfl_xor_sync(0xffffffffu, p, 4);
        float ex = __expf(p);
        den += ex;
        #pragma unroll
        for (int j = 0; j < 8; j++) acc[j] = fmaf(xl8[j], ex, acc[j]);
        s_cur = s_nxt; ep_cur = ep_nxt; e = en;
    }

    float inv = 1.f / (den + 1e-16f);
    #pragma unroll
    for (int j = 0; j < 8; j++) {
        float v = acc[j] * inv;
        v += __shfl_xor_sync(0xffffffffu, v, 8);
        v += __shfl_xor_sync(0xffffffffu, v, 16);
        acc[j] = v;
    }
    if (lane < 8) {
        float4 b0 = *(const float4*)(bias + 8 * lane);
        float4 b1 = *(const float4*)(bias + 8 * lane + 4);
        float o0 = fmaxf(acc[0] * 0.25f + b0.x, 0.f);
        float o1 = fmaxf(acc[1] * 0.25f + b0.y, 0.f);
        float o2 = fmaxf(acc[2] * 0.25f + b0.z, 0.f);
        float o3 = fmaxf(acc[3] * 0.25f + b0.w, 0.f);
        float o4 = fmaxf(acc[4] * 0.25f + b1.x, 0.f);
        float o5 = fmaxf(acc[5] * 0.25f + b1.y, 0.f);
        float o6 = fmaxf(acc[6] * 0.25f + b1.z, 0.f);
        float o7 = fmaxf(acc[7] * 0.25f + b1.w, 0.f);
        float* hp = g_h + (size_t)n * HID + 8 * lane;
        *(float4*)hp       = make_float4(o0, o1, o2, o3);
        *(float4*)(hp + 4) = make_float4(o4, o5, o6, o7);
    }
}

// ---------------- graph pooling -------------------------------------------------
__global__ void pool_kernel(const int* __restrict__ batch) {
    int idx = blockIdx.x * blockDim.x + threadIdx.x;
    if (idx >= NN * HID) return;
    int n = idx >> 6, c = idx & 63;
    int g = batch[n];
    atomicAdd(&g_pool[g * HID + c], g_h[idx]);
    if (c == 0) atomicAdd(&g_cnt[g], 1.f);
}

// ---------------- head ----------------------------------------------------------
__global__ __launch_bounds__(64) void final_kernel(
        const float* __restrict__ W_fc, const float* __restrict__ b_fc,
        const float* __restrict__ W_res, const float* __restrict__ b_res,
        const float* __restrict__ W_time, const float* __restrict__ b_time,
        float* __restrict__ out) {
    int g = blockIdx.x;
    int c = threadIdx.x;
    float inv = 1.f / fmaxf(g_cnt[g], 1.f);
    float acc = b_fc[c];
    for (int k = 0; k < HID; k++)
        acc = fmaf(g_pool[g * HID + k] * inv, W_fc[k * HID + c], acc);
    float gv = (acc > 0.f) ? acc : 0.f;
    float r  = gv * W_res[c];
    float tm = gv * W_time[c];
    #pragma unroll
    for (int o = 16; o; o >>= 1) {
        r  += __shfl_xor_sync(0xffffffffu, r, o);
        tm += __shfl_xor_sync(0xffffffffu, tm, o);
    }
    __shared__ float sr[2], st[2];
    if ((c & 31) == 0) { sr[c >> 5] = r; st[c >> 5] = tm; }
    __syncthreads();
    if (c == 0) {
        out[g * 2 + 0] = sr[0] + sr[1] + b_res[0];
        out[g * 2 + 1] = st[0] + st[1] + b_time[0];
    }
}

// ---------------- cleanup: restore zeroed state for the next replay -------------
__global__ void cleanup_kernel() {
    int idx = blockIdx.x * blockDim.x + threadIdx.x;
    int stride = gridDim.x * blockDim.x;
    for (int i = idx; i < NN; i += stride) g_hist[i] = 0;
    for (int i = idx; i < GG * HID; i += stride) g_pool[i] = 0.f;
    for (int i = idx; i < GG; i += stride) g_cnt[i] = 0.f;
}

// ---------------- launcher -------------------------------------------------------
extern "C" void kernel_launch(void* const* d_in, const int* in_sizes, int n_in,
                              void* d_out, int out_size) {
    int I_x, I_ea, I_ei, I_b, I_Wet, I_bet, I_Wuw, I_buw, I_Wua, I_bua;
    int I_Wl0, I_bl0, I_Wr0, I_br0, I_att0, I_We0, I_bias0;
    int I_Wl1, I_bl1, I_Wr1, I_br1, I_att1, I_We1, I_bias1;
    int I_Wfc, I_bfc, I_Wres, I_bres, I_Wtime, I_btime;
    if (in_sizes[0] == 2) {
        I_Wet = 0; I_Wfc = 1; I_Wres = 2; I_Wtime = 3; I_Wua = 4; I_Wuw = 5;
        I_We0 = 6; I_We1 = 7; I_Wl0 = 8; I_Wl1 = 9; I_Wr0 = 10; I_Wr1 = 11;
        I_att0 = 12; I_att1 = 13;
        I_bet = 14; I_bfc = 15; I_bres = 16; I_btime = 17; I_bua = 18; I_buw = 19;
        I_b = 20; I_bias0 = 21; I_bias1 = 22;
        I_bl0 = 23; I_bl1 = 24; I_br0 = 25; I_br1 = 26;
        I_ea = 27; I_ei = 28; I_x = 29;
    } else if (in_sizes[2] == 2 * EE) {
        I_x = 0; I_ea = 1; I_ei = 2; I_b = 3;
        I_Wet = 4; I_bet = 5; I_Wuw = 6; I_buw = 7; I_Wua = 8; I_bua = 9;
        I_Wl0 = 10; I_bl0 = 11; I_Wr0 = 12; I_br0 = 13; I_att0 = 14; I_We0 = 15; I_bias0 = 16;
        I_Wl1 = 17; I_bl1 = 18; I_Wr1 = 19; I_br1 = 20; I_att1 = 21; I_We1 = 22; I_bias1 = 23;
        I_Wfc = 24; I_bfc = 25; I_Wres = 26; I_bres = 27; I_Wtime = 28; I_btime = 29;
    } else {
        I_x = 0; I_ea = 1;
        I_Wet = 2; I_bet = 3; I_Wuw = 4; I_buw = 5; I_Wua = 6; I_bua = 7;
        I_Wl0 = 8; I_bl0 = 9; I_Wr0 = 10; I_br0 = 11; I_att0 = 12; I_We0 = 13; I_bias0 = 14;
        I_Wl1 = 15; I_bl1 = 16; I_Wr1 = 17; I_br1 = 18; I_att1 = 19; I_We1 = 20; I_bias1 = 21;
        I_Wfc = 22; I_bfc = 23; I_Wres = 24; I_bres = 25; I_Wtime = 26; I_btime = 27;
        I_ei = 28; I_b = 29;
    }

    const float* x        = (const float*)d_in[I_x];
    const float* edge_attr= (const float*)d_in[I_ea];
    const int*   edge_idx = (const int*)  d_in[I_ei];
    const int*   batch    = (const int*)  d_in[I_b];
    const float* W_et = (const float*)d_in[I_Wet], *b_et = (const float*)d_in[I_bet];
    const float* W_uw = (const float*)d_in[I_Wuw], *b_uw = (const float*)d_in[I_buw];
    const float* W_ua = (const float*)d_in[I_Wua], *b_ua = (const float*)d_in[I_bua];
    const float* Wl0 = (const float*)d_in[I_Wl0], *bl0 = (const float*)d_in[I_bl0];
    const float* Wr0 = (const float*)d_in[I_Wr0], *br0 = (const float*)d_in[I_br0];
    const float* att0 = (const float*)d_in[I_att0], *We0 = (const float*)d_in[I_We0];
    const float* bias0 = (const float*)d_in[I_bias0];
    const float* Wl1 = (const float*)d_in[I_Wl1], *bl1 = (const float*)d_in[I_bl1];
    const float* Wr1 = (const float*)d_in[I_Wr1], *br1 = (const float*)d_in[I_br1];
    const float* att1 = (const float*)d_in[I_att1], *We1 = (const float*)d_in[I_We1];
    const float* bias1 = (const float*)d_in[I_bias1];
    const float* W_fc = (const float*)d_in[I_Wfc], *b_fc = (const float*)d_in[I_bfc];
    const float* W_res = (const float*)d_in[I_Wres], *b_res = (const float*)d_in[I_bres];
    const float* W_time = (const float*)d_in[I_Wtime], *b_time = (const float*)d_in[I_btime];
    float* out = (float*)d_out;

    // launch order: position 4 is the ncu-profiled launch -> edge_kernel layer 0.
    hist_kernel<<<(EE + 255) / 256, 256>>>(edge_idx);                 // 1
    gemm_scan_kernel<<<NN / 16 + 1, 256>>>(x, Wl0, bl0, Wr0, br0);    // 2 (GEMM0 + scan)
    scatter_kernel<<<(EE + 255) / 256, 256>>>(edge_idx, edge_attr,    // 3
                                              W_et, b_et, W_uw, b_uw, W_ua, b_ua);
    edge_kernel<<<(NN + 7) / 8, 256>>>(att0, We0, bias0);             // 4  <- profiled
    gemm_f2_kernel1<<<NN / 16, 256>>>(Wl1, bl1, Wr1, br1);            // 5
    edge_kernel<<<(NN + 7) / 8, 256>>>(att1, We1, bias1);             // 6
    pool_kernel<<<(NN * HID + 255) / 256, 256>>>(batch);              // 7
    final_kernel<<<GG, 64>>>(W_fc, b_fc, W_res, b_res, W_time, b_time, out); // 8
    cleanup_kernel<<<128, 256>>>();                                   // 9
}

// round 14
// speedup vs baseline: 1.7341x; 1.0664x over previous
#include <cuda_runtime.h>
#include <cuda_bf16.h>
#include <cstdint>
#include <math.h>

// Problem constants
#define NN 50000
#define EE 400000
#define GG 64
#define IN_CH 128
#define HID 64
#define NHEAD 4
#define CH256 256   // NHEAD*HID
#define EDGE_BLOCKS 782                 // persistent edge warps: 782*8 = 6256

typedef unsigned long long ull;

// ---------------- scratch (static __device__ globals; no allocation) ----------
// g_hist/g_pool/g_cnt zero at module load; cleanup_kernel re-zeroes at the END
// of every launch so all replays see identical initial state.
__device__ __align__(16) float  g_xl[NN * CH256];     // 51.2 MB
__device__ __align__(16) float  g_xr[NN * CH256];     // 51.2 MB
__device__ __align__(16) float  g_h [NN * HID];       // 12.8 MB
__device__ __align__(16) int    g_hist[NN];
__device__ __align__(16) int    g_off [NN + 4];
__device__ __align__(16) int    g_cur [NN + 4];
__device__ __align__(16) int    g_csr_src[EE];
__device__ __align__(16) float4 g_csr_eap[EE];
__device__ __align__(16) float  g_pool[GG * HID];
__device__ __align__(16) float  g_cnt [GG];

// ---------------- packed f32x2 helpers ------------------------------------------
#define FFMA2(d, a, b) \
    asm("fma.rn.f32x2 %0, %1, %2, %0;" : "+l"(d) : "l"(a), "l"(b))
#define DUP2(d, f) \
    asm("mov.b64 %0, {%1, %1};" : "=l"(d) : "f"(f))
__device__ __forceinline__ float f2lo(ull v) { return __uint_as_float((uint32_t)v); }
__device__ __forceinline__ float f2hi(ull v) { return __uint_as_float((uint32_t)(v >> 32)); }

// ---------------- histogram of dst ---------------------------------------------
__global__ void hist_kernel(const int* __restrict__ edge_index) {
    int e = blockIdx.x * blockDim.x + threadIdx.x;
    if (e < EE) atomicAdd(&g_hist[edge_index[EE + e]], 1);
}

// ---------------- 256-thread block scan ------------------------------------------
__device__ void scan_block256() {
    __shared__ __align__(16) int wsum[8];
    __shared__ int s_carry;
    int t = threadIdx.x, lane = t & 31, wid = t >> 5;
    if (t == 0) s_carry = 0;
    __syncthreads();
    for (int base = 0; base < NN; base += 2048) {
        int i0 = base + t * 8;
        int v[8];
        if (i0 + 8 <= NN) {
            int4 a = *(const int4*)(g_hist + i0);
            int4 b = *(const int4*)(g_hist + i0 + 4);
            v[0]=a.x; v[1]=a.y; v[2]=a.z; v[3]=a.w;
            v[4]=b.x; v[5]=b.y; v[6]=b.z; v[7]=b.w;
        } else {
            #pragma unroll
            for (int j = 0; j < 8; j++) v[j] = (i0 + j < NN) ? g_hist[i0 + j] : 0;
        }
        int pre[8]; int s = 0;
        #pragma unroll
        for (int j = 0; j < 8; j++) { pre[j] = s; s += v[j]; }
        int x = s;
        #pragma unroll
        for (int o = 1; o < 32; o <<= 1) {
            int y = __shfl_up_sync(0xffffffffu, x, o);
            if (lane >= o) x += y;
        }
        if (lane == 31) wsum[wid] = x;
        __syncthreads();
        if (t == 0) {
            int c = s_carry;
            #pragma unroll
            for (int w8 = 0; w8 < 8; w8++) { int tmp = wsum[w8]; wsum[w8] = c; c += tmp; }
            s_carry = c;
        }
        __syncthreads();
        int toff = wsum[wid] + (x - s);
        #pragma unroll
        for (int j = 0; j < 8; j++) {
            int i = i0 + j;
            if (i < NN) { int e = toff + pre[j]; g_off[i] = e; g_cur[i] = e; }
        }
        __syncthreads();
    }
    if (t == 0) g_off[NN] = s_carry;
}

// ---------------- FFMA2 GEMM body ------------------------------------------------
template <int K, bool USE_GH>
__device__ __forceinline__ void gemm_body(int bx,
        const float* __restrict__ x,
        const float* __restrict__ Wl, const float* __restrict__ bl,
        const float* __restrict__ Wr, const float* __restrict__ br,
        float* xsT) {
    int t = threadIdx.x;
    int node0 = bx * 16;
    const float* __restrict__ src = USE_GH ? (const float*)g_h : x;
    for (int i = t; i < 16 * K; i += 256) {
        int n = i / K, k = i % K;
        xsT[k * 20 + n] = src[(size_t)(node0 + n) * K + k];
    }
    __syncthreads();

    ull accl[8], accr[8];
    #pragma unroll
    for (int p = 0; p < 8; p++) { accl[p] = 0ull; accr[p] = 0ull; }

    #pragma unroll 2
    for (int k = 0; k < K; k++) {
        const ulonglong2* rp = (const ulonglong2*)(xsT + k * 20);
        ulonglong2 q0 = rp[0], q1 = rp[1], q2 = rp[2], q3 = rp[3];
        float wl = __ldg(&Wl[k * CH256 + t]);
        float wr = __ldg(&Wr[k * CH256 + t]);
        ull wld, wrd;
        DUP2(wld, wl); DUP2(wrd, wr);
        FFMA2(accl[0], q0.x, wld); FFMA2(accl[1], q0.y, wld);
        FFMA2(accl[2], q1.x, wld); FFMA2(accl[3], q1.y, wld);
        FFMA2(accl[4], q2.x, wld); FFMA2(accl[5], q2.y, wld);
        FFMA2(accl[6], q3.x, wld); FFMA2(accl[7], q3.y, wld);
        FFMA2(accr[0], q0.x, wrd); FFMA2(accr[1], q0.y, wrd);
        FFMA2(accr[2], q1.x, wrd); FFMA2(accr[3], q1.y, wrd);
        FFMA2(accr[4], q2.x, wrd); FFMA2(accr[5], q2.y, wrd);
        FFMA2(accr[6], q3.x, wrd); FFMA2(accr[7], q3.y, wrd);
    }

    float bbl = bl[t], bbr = br[t];
    #pragma unroll
    for (int p = 0; p < 8; p++) {
        size_t n = node0 + 2 * p;
        g_xl[n * CH256 + t]       = f2lo(accl[p]) + bbl;
        g_xl[(n + 1) * CH256 + t] = f2hi(accl[p]) + bbl;
        g_xr[n * CH256 + t]       = f2lo(accr[p]) + bbr;
        g_xr[(n + 1) * CH256 + t] = f2hi(accr[p]) + bbr;
    }
}

// layer-0 GEMM fused with the CSR scan: block 0 scans, blocks 1.. do GEMM.
__global__ __launch_bounds__(256) void gemm_scan_kernel(
        const float* __restrict__ x,
        const float* __restrict__ Wl, const float* __restrict__ bl,
        const float* __restrict__ Wr, const float* __restrict__ br) {
    __shared__ __align__(16) float xsT[IN_CH * 20];
    if (blockIdx.x == 0) { scan_block256(); return; }
    gemm_body<IN_CH, false>(blockIdx.x - 1, x, Wl, bl, Wr, br, xsT);
}

__global__ __launch_bounds__(256) void gemm_f2_kernel1(
        const float* __restrict__ Wl, const float* __restrict__ bl,
        const float* __restrict__ Wr, const float* __restrict__ br) {
    __shared__ __align__(16) float xsT[HID * 20];
    gemm_body<HID, true>(blockIdx.x, nullptr, Wl, bl, Wr, br, xsT);
}

// ---------------- scatter edges into CSR + edge-attr projection ---------------
__global__ void scatter_kernel(const int* __restrict__ edge_index,
                               const float* __restrict__ edge_attr,
                               const float* __restrict__ W_et, const float* __restrict__ b_et,
                               const float* __restrict__ W_uw, const float* __restrict__ b_uw,
                               const float* __restrict__ W_ua, const float* __restrict__ b_ua) {
    int e = blockIdx.x * blockDim.x + threadIdx.x;
    if (e >= EE) return;
    int s = edge_index[e];
    int d = edge_index[EE + e];
    int pos = atomicAdd(&g_cur[d], 1);
    g_csr_src[pos] = s;
    float et = edge_attr[2 * e];
    float uw = edge_attr[2 * e + 1];
    float ua = 1.f / (1.f + __expf(-(uw * W_ua[0] + b_ua[0])));
    float4 ep;
    ep.x = et * W_et[0] + b_et[0];
    ep.y = et * W_et[1] + b_et[1];
    ep.z = (uw * W_uw[0] + b_uw[0]) * ua;
    ep.w = (uw * W_uw[1] + b_uw[1]) * ua;
    g_csr_eap[pos] = ep;
}

// ---------------- persistent warp-per-node GATv2 edge stage ---------------------
// 6256 persistent warps, each loops over nodes (stride = total warps). We/att
// register setup happens ONCE per warp. Per node: 3-deep software pipeline —
// csr/eap prefetched 2 edges ahead, xl row prefetched 1 edge ahead (MLP=2 on
// the expensive gather).
__global__ __launch_bounds__(256) void edge_kernel(
        const float* __restrict__ att, const float* __restrict__ We,
        const float* __restrict__ bias) {
    int t = threadIdx.x;
    int w = t >> 5, lane = t & 31;
    int cb = 8 * lane;
    int gw = blockIdx.x * 8 + w;
    const int NW = EDGE_BLOCKS * 8;

    float we0[8], we1[8], we2[8], we3[8], av[8];
    {
        float4 p, q;
        p = *(const float4*)(We + 0 * CH256 + cb); q = *(const float4*)(We + 0 * CH256 + cb + 4);
        we0[0]=p.x; we0[1]=p.y; we0[2]=p.z; we0[3]=p.w; we0[4]=q.x; we0[5]=q.y; we0[6]=q.z; we0[7]=q.w;
        p = *(const float4*)(We + 1 * CH256 + cb); q = *(const float4*)(We + 1 * CH256 + cb + 4);
        we1[0]=p.x; we1[1]=p.y; we1[2]=p.z; we1[3]=p.w; we1[4]=q.x; we1[5]=q.y; we1[6]=q.z; we1[7]=q.w;
        p = *(const float4*)(We + 2 * CH256 + cb); q = *(const float4*)(We + 2 * CH256 + cb + 4);
        we2[0]=p.x; we2[1]=p.y; we2[2]=p.z; we2[3]=p.w; we2[4]=q.x; we2[5]=q.y; we2[6]=q.z; we2[7]=q.w;
        p = *(const float4*)(We + 3 * CH256 + cb); q = *(const float4*)(We + 3 * CH256 + cb + 4);
        we3[0]=p.x; we3[1]=p.y; we3[2]=p.z; we3[3]=p.w; we3[4]=q.x; we3[5]=q.y; we3[6]=q.z; we3[7]=q.w;
        p = *(const float4*)(att + cb); q = *(const float4*)(att + cb + 4);
        av[0]=p.x; av[1]=p.y; av[2]=p.z; av[3]=p.w; av[4]=q.x; av[5]=q.y; av[6]=q.z; av[7]=q.w;
    }
    float4 bv0, bv1;
    if (lane < 8) {
        bv0 = *(const float4*)(bias + 8 * lane);
        bv1 = *(const float4*)(bias + 8 * lane + 4);
    }

    for (int n = gw; n < NN; n += NW) {
        float xr8[8];
        {
            const float* xp = g_xr + (size_t)n * CH256 + cb;
            float4 p = *(const float4*)xp, q = *(const float4*)(xp + 4);
            xr8[0]=p.x; xr8[1]=p.y; xr8[2]=p.z; xr8[3]=p.w;
            xr8[4]=q.x; xr8[5]=q.y; xr8[6]=q.z; xr8[7]=q.w;
        }
        float acc[8];
        #pragma unroll
        for (int j = 0; j < 8; j++) acc[j] = 0.f;
        float den = 0.f;
        int e0 = g_off[n], e1 = g_off[n + 1];

        // pipeline warm-up: edge e (csr+eap+xl), edge e+1 (csr+eap)
        int e = e0;
        int s1 = 0; float4 ep0 = make_float4(0.f,0.f,0.f,0.f), ep1 = ep0;
        float4 xa = ep0, xb = ep0;
        if (e < e1) {
            int s0 = __ldg(&g_csr_src[e]); ep0 = g_csr_eap[e];
            const float* xlp = g_xl + (size_t)s0 * CH256 + cb;
            xa = *(const float4*)xlp; xb = *(const float4*)(xlp + 4);
        }
        if (e + 1 < e1) { s1 = __ldg(&g_csr_src[e + 1]); ep1 = g_csr_eap[e + 1]; }

        while (e < e1) {
            // prefetch xl for e+1 and csr/eap for e+2
            float4 xa_n = xa, xb_n = xb;
            if (e + 1 < e1) {
                const float* xlp = g_xl + (size_t)s1 * CH256 + cb;
                xa_n = *(const float4*)xlp; xb_n = *(const float4*)(xlp + 4);
            }
            int s2 = s1; float4 ep2 = ep1;
            if (e + 2 < e1) { s2 = __ldg(&g_csr_src[e + 2]); ep2 = g_csr_eap[e + 2]; }

            float xl8[8] = {xa.x, xa.y, xa.z, xa.w, xb.x, xb.y, xb.z, xb.w};
            float p = 0.f;
            #pragma unroll
            for (int j = 0; j < 8; j++) {
                float ee = fmaf(ep0.x, we0[j], fmaf(ep0.y, we1[j],
                           fmaf(ep0.z, we2[j], ep0.w * we3[j])));
                float m = xl8[j] + xr8[j] + ee;
                m = (m > 0.f) ? m : 0.2f * m;
                p = fmaf(m, av[j], p);
            }
            p += __shfl_xor_sync(0xffffffffu, p, 1);
            p += __shfl_xor_sync(0xffffffffu, p, 2);
            p += __shfl_xor_sync(0xffffffffu, p, 4);
            float ex = __expf(p);
            den += ex;
            #pragma unroll
            for (int j = 0; j < 8; j++) acc[j] = fmaf(xl8[j], ex, acc[j]);

            xa = xa_n; xb = xb_n; ep0 = ep1; ep1 = ep2; s1 = s2;
            e++;
        }

        float inv = 1.f / (den + 1e-16f);
        #pragma unroll
        for (int j = 0; j < 8; j++) {
            float v = acc[j] * inv;
            v += __shfl_xor_sync(0xffffffffu, v, 8);
            v += __shfl_xor_sync(0xffffffffu, v, 16);
            acc[j] = v;
        }
        if (lane < 8) {
            float o0 = fmaxf(acc[0] * 0.25f + bv0.x, 0.f);
            float o1 = fmaxf(acc[1] * 0.25f + bv0.y, 0.f);
            float o2 = fmaxf(acc[2] * 0.25f + bv0.z, 0.f);
            float o3 = fmaxf(acc[3] * 0.25f + bv0.w, 0.f);
            float o4 = fmaxf(acc[4] * 0.25f + bv1.x, 0.f);
            float o5 = fmaxf(acc[5] * 0.25f + bv1.y, 0.f);
            float o6 = fmaxf(acc[6] * 0.25f + bv1.z, 0.f);
            float o7 = fmaxf(acc[7] * 0.25f + bv1.w, 0.f);
            float* hp = g_h + (size_t)n * HID + 8 * lane;
            *(float4*)hp       = make_float4(o0, o1, o2, o3);
            *(float4*)(hp + 4) = make_float4(o4, o5, o6, o7);
        }
    }
}

// ---------------- graph pooling -------------------------------------------------
__global__ void pool_kernel(const int* __restrict__ batch) {
    int idx = blockIdx.x * blockDim.x + threadIdx.x;
    if (idx >= NN * HID) return;
    int n = idx >> 6, c = idx & 63;
    int g = batch[n];
    atomicAdd(&g_pool[g * HID + c], g_h[idx]);
    if (c == 0) atomicAdd(&g_cnt[g], 1.f);
}

// ---------------- head ----------------------------------------------------------
__global__ __launch_bounds__(64) void final_kernel(
        const float* __restrict__ W_fc, const float* __restrict__ b_fc,
        const float* __restrict__ W_res, const float* __restrict__ b_res,
        const float* __restrict__ W_time, const float* __restrict__ b_time,
        float* __restrict__ out) {
    int g = blockIdx.x;
    int c = threadIdx.x;
    float inv = 1.f / fmaxf(g_cnt[g], 1.f);
    float acc = b_fc[c];
    for (int k = 0; k < HID; k++)
        acc = fmaf(g_pool[g * HID + k] * inv, W_fc[k * HID + c], acc);
    float gv = (acc > 0.f) ? acc : 0.f;
    float r  = gv * W_res[c];
    float tm = gv * W_time[c];
    #pragma unroll
    for (int o = 16; o; o >>= 1) {
        r  += __shfl_xor_sync(0xffffffffu, r, o);
        tm += __shfl_xor_sync(0xffffffffu, tm, o);
    }
    __shared__ float sr[2], st[2];
    if ((c & 31) == 0) { sr[c >> 5] = r; st[c >> 5] = tm; }
    __syncthreads();
    if (c == 0) {
        out[g * 2 + 0] = sr[0] + sr[1] + b_res[0];
        out[g * 2 + 1] = st[0] + st[1] + b_time[0];
    }
}

// ---------------- cleanup: restore zeroed state for the next replay -------------
__global__ void cleanup_kernel() {
    int idx = blockIdx.x * blockDim.x + threadIdx.x;
    int stride = gridDim.x * blockDim.x;
    for (int i = idx; i < NN; i += stride) g_hist[i] = 0;
    for (int i = idx; i < GG * HID; i += stride) g_pool[i] = 0.f;
    for (int i = idx; i < GG; i += stride) g_cnt[i] = 0.f;
}

// ---------------- launcher -------------------------------------------------------
extern "C" void kernel_launch(void* const* d_in, const int* in_sizes, int n_in,
                              void* d_out, int out_size) {
    int I_x, I_ea, I_ei, I_b, I_Wet, I_bet, I_Wuw, I_buw, I_Wua, I_bua;
    int I_Wl0, I_bl0, I_Wr0, I_br0, I_att0, I_We0, I_bias0;
    int I_Wl1, I_bl1, I_Wr1, I_br1, I_att1, I_We1, I_bias1;
    int I_Wfc, I_bfc, I_Wres, I_bres, I_Wtime, I_btime;
    if (in_sizes[0] == 2) {
        I_Wet = 0; I_Wfc = 1; I_Wres = 2; I_Wtime = 3; I_Wua = 4; I_Wuw = 5;
        I_We0 = 6; I_We1 = 7; I_Wl0 = 8; I_Wl1 = 9; I_Wr0 = 10; I_Wr1 = 11;
        I_att0 = 12; I_att1 = 13;
        I_bet = 14; I_bfc = 15; I_bres = 16; I_btime = 17; I_bua = 18; I_buw = 19;
        I_b = 20; I_bias0 = 21; I_bias1 = 22;
        I_bl0 = 23; I_bl1 = 24; I_br0 = 25; I_br1 = 26;
        I_ea = 27; I_ei = 28; I_x = 29;
    } else if (in_sizes[2] == 2 * EE) {
        I_x = 0; I_ea = 1; I_ei = 2; I_b = 3;
        I_Wet = 4; I_bet = 5; I_Wuw = 6; I_buw = 7; I_Wua = 8; I_bua = 9;
        I_Wl0 = 10; I_bl0 = 11; I_Wr0 = 12; I_br0 = 13; I_att0 = 14; I_We0 = 15; I_bias0 = 16;
        I_Wl1 = 17; I_bl1 = 18; I_Wr1 = 19; I_br1 = 20; I_att1 = 21; I_We1 = 22; I_bias1 = 23;
        I_Wfc = 24; I_bfc = 25; I_Wres = 26; I_bres = 27; I_Wtime = 28; I_btime = 29;
    } else {
        I_x = 0; I_ea = 1;
        I_Wet = 2; I_bet = 3; I_Wuw = 4; I_buw = 5; I_Wua = 6; I_bua = 7;
        I_Wl0 = 8; I_bl0 = 9; I_Wr0 = 10; I_br0 = 11; I_att0 = 12; I_We0 = 13; I_bias0 = 14;
        I_Wl1 = 15; I_bl1 = 16; I_Wr1 = 17; I_br1 = 18; I_att1 = 19; I_We1 = 20; I_bias1 = 21;
        I_Wfc = 22; I_bfc = 23; I_Wres = 24; I_bres = 25; I_Wtime = 26; I_btime = 27;
        I_ei = 28; I_b = 29;
    }

    const float* x        = (const float*)d_in[I_x];
    const float* edge_attr= (const float*)d_in[I_ea];
    const int*   edge_idx = (const int*)  d_in[I_ei];
    const int*   batch    = (const int*)  d_in[I_b];
    const float* W_et = (const float*)d_in[I_Wet], *b_et = (const float*)d_in[I_bet];
    const float* W_uw = (const float*)d_in[I_Wuw], *b_uw = (const float*)d_in[I_buw];
    const float* W_ua = (const float*)d_in[I_Wua], *b_ua = (const float*)d_in[I_bua];
    const float* Wl0 = (const float*)d_in[I_Wl0], *bl0 = (const float*)d_in[I_bl0];
    const float* Wr0 = (const float*)d_in[I_Wr0], *br0 = (const float*)d_in[I_br0];
    const float* att0 = (const float*)d_in[I_att0], *We0 = (const float*)d_in[I_We0];
    const float* bias0 = (const float*)d_in[I_bias0];
    const float* Wl1 = (const float*)d_in[I_Wl1], *bl1 = (const float*)d_in[I_bl1];
    const float* Wr1 = (const float*)d_in[I_Wr1], *br1 = (const float*)d_in[I_br1];
    const float* att1 = (const float*)d_in[I_att1], *We1 = (const float*)d_in[I_We1];
    const float* bias1 = (const float*)d_in[I_bias1];
    const float* W_fc = (const float*)d_in[I_Wfc], *b_fc = (const float*)d_in[I_bfc];
    const float* W_res = (const float*)d_in[I_Wres], *b_res = (const float*)d_in[I_bres];
    const float* W_time = (const float*)d_in[I_Wtime], *b_time = (const float*)d_in[I_btime];
    float* out = (float*)d_out;

    // launch order: position 4 is the ncu-profiled launch -> edge_kernel layer 0.
    hist_kernel<<<(EE + 255) / 256, 256>>>(edge_idx);                 // 1
    gemm_scan_kernel<<<NN / 16 + 1, 256>>>(x, Wl0, bl0, Wr0, br0);    // 2 (GEMM0 + scan)
    scatter_kernel<<<(EE + 255) / 256, 256>>>(edge_idx, edge_attr,    // 3
                                              W_et, b_et, W_uw, b_uw, W_ua, b_ua);
    edge_kernel<<<EDGE_BLOCKS, 256>>>(att0, We0, bias0);              // 4  <- profiled
    gemm_f2_kernel1<<<NN / 16, 256>>>(Wl1, bl1, Wr1, br1);            // 5
    edge_kernel<<<EDGE_BLOCKS, 256>>>(att1, We1, bias1);              // 6
    pool_kernel<<<(NN * HID + 255) / 256, 256>>>(batch);              // 7
    final_kernel<<<GG, 64>>>(W_fc, b_fc, W_res, b_res, W_time, b_time, out); // 8
    cleanup_kernel<<<128, 256>>>();                                   // 9
}

// round 15
// speedup vs baseline: 1.7641x; 1.0173x over previous
#include <cuda_runtime.h>
#include <cuda_bf16.h>
#include <cstdint>
#include <math.h>

// Problem constants
#define NN 50000
#define EE 400000
#define GG 64
#define IN_CH 128
#define HID 64
#define NHEAD 4
#define CH256 256   // NHEAD*HID
#define EDGE_BLOCKS 782                 // persistent edge warps: 782*8 = 6256

typedef unsigned long long ull;

// ---------------- scratch (static __device__ globals; no allocation) ----------
__device__ __align__(16) float  g_xl[NN * CH256];     // 51.2 MB
__device__ __align__(16) float  g_xr[NN * CH256];     // 51.2 MB
__device__ __align__(16) float  g_h [NN * HID];       // 12.8 MB
__device__ __align__(16) int    g_hist[NN];
__device__ __align__(16) int    g_off [NN + 4];
__device__ __align__(16) int    g_cur [NN + 4];
__device__ __align__(16) int    g_csr_src[EE];
__device__ __align__(16) float4 g_csr_eap[EE];
__device__ __align__(16) float  g_pool[GG * HID];
__device__ __align__(16) float  g_cnt [GG];

// ---------------- packed f32x2 helpers ------------------------------------------
#define FFMA2(d, a, b) \
    asm("fma.rn.f32x2 %0, %1, %2, %0;" : "+l"(d) : "l"(a), "l"(b))
#define FFMA2D(d, a, b, c) \
    asm("fma.rn.f32x2 %0, %1, %2, %3;" : "=l"(d) : "l"(a), "l"(b), "l"(c))
#define ADD2(d, a, b) \
    asm("add.rn.f32x2 %0, %1, %2;" : "=l"(d) : "l"(a), "l"(b))
#define MUL2(d, a, b) \
    asm("mul.rn.f32x2 %0, %1, %2;" : "=l"(d) : "l"(a), "l"(b))
#define DUP2(d, f) \
    asm("mov.b64 %0, {%1, %1};" : "=l"(d) : "f"(f))
__device__ __forceinline__ float f2lo(ull v) { return __uint_as_float((uint32_t)v); }
__device__ __forceinline__ float f2hi(ull v) { return __uint_as_float((uint32_t)(v >> 32)); }

// ---------------- histogram of dst ---------------------------------------------
__global__ void hist_kernel(const int* __restrict__ edge_index) {
    int e = blockIdx.x * blockDim.x + threadIdx.x;
    if (e < EE) atomicAdd(&g_hist[edge_index[EE + e]], 1);
}

// ---------------- 256-thread block scan ------------------------------------------
__device__ void scan_block256() {
    __shared__ __align__(16) int wsum[8];
    __shared__ int s_carry;
    int t = threadIdx.x, lane = t & 31, wid = t >> 5;
    if (t == 0) s_carry = 0;
    __syncthreads();
    for (int base = 0; base < NN; base += 2048) {
        int i0 = base + t * 8;
        int v[8];
        if (i0 + 8 <= NN) {
            int4 a = *(const int4*)(g_hist + i0);
            int4 b = *(const int4*)(g_hist + i0 + 4);
            v[0]=a.x; v[1]=a.y; v[2]=a.z; v[3]=a.w;
            v[4]=b.x; v[5]=b.y; v[6]=b.z; v[7]=b.w;
        } else {
            #pragma unroll
            for (int j = 0; j < 8; j++) v[j] = (i0 + j < NN) ? g_hist[i0 + j] : 0;
        }
        int pre[8]; int s = 0;
        #pragma unroll
        for (int j = 0; j < 8; j++) { pre[j] = s; s += v[j]; }
        int x = s;
        #pragma unroll
        for (int o = 1; o < 32; o <<= 1) {
            int y = __shfl_up_sync(0xffffffffu, x, o);
            if (lane >= o) x += y;
        }
        if (lane == 31) wsum[wid] = x;
        __syncthreads();
        if (t == 0) {
            int c = s_carry;
            #pragma unroll
            for (int w8 = 0; w8 < 8; w8++) { int tmp = wsum[w8]; wsum[w8] = c; c += tmp; }
            s_carry = c;
        }
        __syncthreads();
        int toff = wsum[wid] + (x - s);
        #pragma unroll
        for (int j = 0; j < 8; j++) {
            int i = i0 + j;
            if (i < NN) { int e = toff + pre[j]; g_off[i] = e; g_cur[i] = e; }
        }
        __syncthreads();
    }
    if (t == 0) g_off[NN] = s_carry;
}

// ---------------- FFMA2 GEMM body ------------------------------------------------
template <int K, bool USE_GH>
__device__ __forceinline__ void gemm_body(int bx,
        const float* __restrict__ x,
        const float* __restrict__ Wl, const float* __restrict__ bl,
        const float* __restrict__ Wr, const float* __restrict__ br,
        float* xsT) {
    int t = threadIdx.x;
    int node0 = bx * 16;
    const float* __restrict__ src = USE_GH ? (const float*)g_h : x;
    for (int i = t; i < 16 * K; i += 256) {
        int n = i / K, k = i % K;
        xsT[k * 20 + n] = src[(size_t)(node0 + n) * K + k];
    }
    __syncthreads();

    ull accl[8], accr[8];
    #pragma unroll
    for (int p = 0; p < 8; p++) { accl[p] = 0ull; accr[p] = 0ull; }

    #pragma unroll 2
    for (int k = 0; k < K; k++) {
        const ulonglong2* rp = (const ulonglong2*)(xsT + k * 20);
        ulonglong2 q0 = rp[0], q1 = rp[1], q2 = rp[2], q3 = rp[3];
        float wl = __ldg(&Wl[k * CH256 + t]);
        float wr = __ldg(&Wr[k * CH256 + t]);
        ull wld, wrd;
        DUP2(wld, wl); DUP2(wrd, wr);
        FFMA2(accl[0], q0.x, wld); FFMA2(accl[1], q0.y, wld);
        FFMA2(accl[2], q1.x, wld); FFMA2(accl[3], q1.y, wld);
        FFMA2(accl[4], q2.x, wld); FFMA2(accl[5], q2.y, wld);
        FFMA2(accl[6], q3.x, wld); FFMA2(accl[7], q3.y, wld);
        FFMA2(accr[0], q0.x, wrd); FFMA2(accr[1], q0.y, wrd);
        FFMA2(accr[2], q1.x, wrd); FFMA2(accr[3], q1.y, wrd);
        FFMA2(accr[4], q2.x, wrd); FFMA2(accr[5], q2.y, wrd);
        FFMA2(accr[6], q3.x, wrd); FFMA2(accr[7], q3.y, wrd);
    }

    float bbl = bl[t], bbr = br[t];
    #pragma unroll
    for (int p = 0; p < 8; p++) {
        size_t n = node0 + 2 * p;
        g_xl[n * CH256 + t]       = f2lo(accl[p]) + bbl;
        g_xl[(n + 1) * CH256 + t] = f2hi(accl[p]) + bbl;
        g_xr[n * CH256 + t]       = f2lo(accr[p]) + bbr;
        g_xr[(n + 1) * CH256 + t] = f2hi(accr[p]) + bbr;
    }
}

// layer-0 GEMM fused with the CSR scan: block 0 scans, blocks 1.. do GEMM.
__global__ __launch_bounds__(256) void gemm_scan_kernel(
        const float* __restrict__ x,
        const float* __restrict__ Wl, const float* __restrict__ bl,
        const float* __restrict__ Wr, const float* __restrict__ br) {
    __shared__ __align__(16) float xsT[IN_CH * 20];
    if (blockIdx.x == 0) { scan_block256(); return; }
    gemm_body<IN_CH, false>(blockIdx.x - 1, x, Wl, bl, Wr, br, xsT);
}

__global__ __launch_bounds__(256) void gemm_f2_kernel1(
        const float* __restrict__ Wl, const float* __restrict__ bl,
        const float* __restrict__ Wr, const float* __restrict__ br) {
    __shared__ __align__(16) float xsT[HID * 20];
    gemm_body<HID, true>(blockIdx.x, nullptr, Wl, bl, Wr, br, xsT);
}

// ---------------- scatter edges into CSR + edge-attr projection ---------------
__global__ void scatter_kernel(const int* __restrict__ edge_index,
                               const float* __restrict__ edge_attr,
                               const float* __restrict__ W_et, const float* __restrict__ b_et,
                               const float* __restrict__ W_uw, const float* __restrict__ b_uw,
                               const float* __restrict__ W_ua, const float* __restrict__ b_ua) {
    int e = blockIdx.x * blockDim.x + threadIdx.x;
    if (e >= EE) return;
    int s = edge_index[e];
    int d = edge_index[EE + e];
    int pos = atomicAdd(&g_cur[d], 1);
    g_csr_src[pos] = s;
    float et = edge_attr[2 * e];
    float uw = edge_attr[2 * e + 1];
    float ua = 1.f / (1.f + __expf(-(uw * W_ua[0] + b_ua[0])));
    float4 ep;
    ep.x = et * W_et[0] + b_et[0];
    ep.y = et * W_et[1] + b_et[1];
    ep.z = (uw * W_uw[0] + b_uw[0]) * ua;
    ep.w = (uw * W_uw[1] + b_uw[1]) * ua;
    g_csr_eap[pos] = ep;
}

// ---------------- persistent warp-per-node edge stage, f32x2-packed math --------
// Per lane: channels cb..cb+7 as 4 f32x2 pairs. ee accumulates from xr (folded
// init), leaky(m) = 0.6m + 0.4|m| (branch-free, exact to fp32 rounding).
__global__ __launch_bounds__(256) void edge_kernel(
        const float* __restrict__ att, const float* __restrict__ We,
        const float* __restrict__ bias) {
    int t = threadIdx.x;
    int w = t >> 5, lane = t & 31;
    int cb = 8 * lane;
    int gw = blockIdx.x * 8 + w;
    const int NW = EDGE_BLOCKS * 8;

    ull we0p[4], we1p[4], we2p[4], we3p[4], avp[4];
    {
        const ulonglong2* p;
        ulonglong2 a, b;
        p = (const ulonglong2*)(We + 0 * CH256 + cb); a = p[0]; b = p[1];
        we0p[0]=a.x; we0p[1]=a.y; we0p[2]=b.x; we0p[3]=b.y;
        p = (const ulonglong2*)(We + 1 * CH256 + cb); a = p[0]; b = p[1];
        we1p[0]=a.x; we1p[1]=a.y; we1p[2]=b.x; we1p[3]=b.y;
        p = (const ulonglong2*)(We + 2 * CH256 + cb); a = p[0]; b = p[1];
        we2p[0]=a.x; we2p[1]=a.y; we2p[2]=b.x; we2p[3]=b.y;
        p = (const ulonglong2*)(We + 3 * CH256 + cb); a = p[0]; b = p[1];
        we3p[0]=a.x; we3p[1]=a.y; we3p[2]=b.x; we3p[3]=b.y;
        p = (const ulonglong2*)(att + cb); a = p[0]; b = p[1];
        avp[0]=a.x; avp[1]=a.y; avp[2]=b.x; avp[3]=b.y;
    }
    ull c06, c04;
    DUP2(c06, 0.6f); DUP2(c04, 0.4f);
    float4 bv0, bv1;
    if (lane < 8) {
        bv0 = *(const float4*)(bias + 8 * lane);
        bv1 = *(const float4*)(bias + 8 * lane + 4);
    }

    for (int n = gw; n < NN; n += NW) {
        ull xrp[4];
        {
            const ulonglong2* p = (const ulonglong2*)(g_xr + (size_t)n * CH256 + cb);
            ulonglong2 a = p[0], b = p[1];
            xrp[0]=a.x; xrp[1]=a.y; xrp[2]=b.x; xrp[3]=b.y;
        }
        ull acc[4] = {0ull, 0ull, 0ull, 0ull};
        float den = 0.f;
        int e0 = g_off[n], e1 = g_off[n + 1];

        // 3-deep pipeline: csr/eap 2 ahead, xl row 1 ahead
        int e = e0;
        int s1 = 0; float4 ep0 = make_float4(0.f,0.f,0.f,0.f), ep1 = ep0;
        ull xp[4] = {0ull, 0ull, 0ull, 0ull};
        if (e < e1) {
            int s0 = __ldg(&g_csr_src[e]); ep0 = g_csr_eap[e];
            const ulonglong2* p = (const ulonglong2*)(g_xl + (size_t)s0 * CH256 + cb);
            ulonglong2 a = p[0], b = p[1];
            xp[0]=a.x; xp[1]=a.y; xp[2]=b.x; xp[3]=b.y;
        }
        if (e + 1 < e1) { s1 = __ldg(&g_csr_src[e + 1]); ep1 = g_csr_eap[e + 1]; }

        while (e < e1) {
            ull xn[4] = {xp[0], xp[1], xp[2], xp[3]};
            if (e + 1 < e1) {
                const ulonglong2* p = (const ulonglong2*)(g_xl + (size_t)s1 * CH256 + cb);
                ulonglong2 a = p[0], b = p[1];
                xn[0]=a.x; xn[1]=a.y; xn[2]=b.x; xn[3]=b.y;
            }
            int s2 = s1; float4 ep2 = ep1;
            if (e + 2 < e1) { s2 = __ldg(&g_csr_src[e + 2]); ep2 = g_csr_eap[e + 2]; }

            ull epx, epy, epz, epw;
            DUP2(epx, ep0.x); DUP2(epy, ep0.y); DUP2(epz, ep0.z); DUP2(epw, ep0.w);
            ull p2 = 0ull;
            #pragma unroll
            for (int i = 0; i < 4; i++) {
                ull ee;
                FFMA2D(ee, epx, we0p[i], xrp[i]);
                FFMA2(ee, epy, we1p[i]);
                FFMA2(ee, epz, we2p[i]);
                FFMA2(ee, epw, we3p[i]);
                ull m; ADD2(m, xp[i], ee);
                ull am = m & 0x7FFFFFFF7FFFFFFFull;     // packed |m|
                ull lk; MUL2(lk, m, c06);
                FFMA2D(lk, am, c04, lk);                 // 0.6m + 0.4|m|
                FFMA2(p2, lk, avp[i]);
            }
            float p = f2lo(p2) + f2hi(p2);
            p += __shfl_xor_sync(0xffffffffu, p, 1);
            p += __shfl_xor_sync(0xffffffffu, p, 2);
            p += __shfl_xor_sync(0xffffffffu, p, 4);
            float ex = __expf(p);
            den += ex;
            ull exd; DUP2(exd, ex);
            #pragma unroll
            for (int i = 0; i < 4; i++) FFMA2(acc[i], xp[i], exd);

            xp[0]=xn[0]; xp[1]=xn[1]; xp[2]=xn[2]; xp[3]=xn[3];
            ep0 = ep1; ep1 = ep2; s1 = s2;
            e++;
        }

        float inv = 1.f / (den + 1e-16f);
        float a8[8];
        #pragma unroll
        for (int i = 0; i < 4; i++) {
            a8[2*i]   = f2lo(acc[i]) * inv;
            a8[2*i+1] = f2hi(acc[i]) * inv;
        }
        #pragma unroll
        for (int j = 0; j < 8; j++) {
            float v = a8[j];
            v += __shfl_xor_sync(0xffffffffu, v, 8);
            v += __shfl_xor_sync(0xffffffffu, v, 16);
            a8[j] = v;
        }
        if (lane < 8) {
            float o0 = fmaxf(a8[0] * 0.25f + bv0.x, 0.f);
            float o1 = fmaxf(a8[1] * 0.25f + bv0.y, 0.f);
            float o2 = fmaxf(a8[2] * 0.25f + bv0.z, 0.f);
            float o3 = fmaxf(a8[3] * 0.25f + bv0.w, 0.f);
            float o4 = fmaxf(a8[4] * 0.25f + bv1.x, 0.f);
            float o5 = fmaxf(a8[5] * 0.25f + bv1.y, 0.f);
            float o6 = fmaxf(a8[6] * 0.25f + bv1.z, 0.f);
            float o7 = fmaxf(a8[7] * 0.25f + bv1.w, 0.f);
            float* hp = g_h + (size_t)n * HID + 8 * lane;
            *(float4*)hp       = make_float4(o0, o1, o2, o3);
            *(float4*)(hp + 4) = make_float4(o4, o5, o6, o7);
        }
    }
}

// ---------------- graph pooling -------------------------------------------------
__global__ void pool_kernel(const int* __restrict__ batch) {
    int idx = blockIdx.x * blockDim.x + threadIdx.x;
    if (idx >= NN * HID) return;
    int n = idx >> 6, c = idx & 63;
    int g = batch[n];
    atomicAdd(&g_pool[g * HID + c], g_h[idx]);
    if (c == 0) atomicAdd(&g_cnt[g], 1.f);
}

// ---------------- head ----------------------------------------------------------
__global__ __launch_bounds__(64) void final_kernel(
        const float* __restrict__ W_fc, const float* __restrict__ b_fc,
        const float* __restrict__ W_res, const float* __restrict__ b_res,
        const float* __restrict__ W_time, const float* __restrict__ b_time,
        float* __restrict__ out) {
    int g = blockIdx.x;
    int c = threadIdx.x;
    float inv = 1.f / fmaxf(g_cnt[g], 1.f);
    float acc = b_fc[c];
    for (int k = 0; k < HID; k++)
        acc = fmaf(g_pool[g * HID + k] * inv, W_fc[k * HID + c], acc);
    float gv = (acc > 0.f) ? acc : 0.f;
    float r  = gv * W_res[c];
    float tm = gv * W_time[c];
    #pragma unroll
    for (int o = 16; o; o >>= 1) {
        r  += __shfl_xor_sync(0xffffffffu, r, o);
        tm += __shfl_xor_sync(0xffffffffu, tm, o);
    }
    __shared__ float sr[2], st[2];
    if ((c & 31) == 0) { sr[c >> 5] = r; st[c >> 5] = tm; }
    __syncthreads();
    if (c == 0) {
        out[g * 2 + 0] = sr[0] + sr[1] + b_res[0];
        out[g * 2 + 1] = st[0] + st[1] + b_time[0];
    }
}

// ---------------- cleanup: restore zeroed state for the next replay -------------
__global__ void cleanup_kernel() {
    int idx = blockIdx.x * blockDim.x + threadIdx.x;
    int stride = gridDim.x * blockDim.x;
    for (int i = idx; i < NN; i += stride) g_hist[i] = 0;
    for (int i = idx; i < GG * HID; i += stride) g_pool[i] = 0.f;
    for (int i = idx; i < GG; i += stride) g_cnt[i] = 0.f;
}

// ---------------- launcher -------------------------------------------------------
extern "C" void kernel_launch(void* const* d_in, const int* in_sizes, int n_in,
                              void* d_out, int out_size) {
    int I_x, I_ea, I_ei, I_b, I_Wet, I_bet, I_Wuw, I_buw, I_Wua, I_bua;
    int I_Wl0, I_bl0, I_Wr0, I_br0, I_att0, I_We0, I_bias0;
    int I_Wl1, I_bl1, I_Wr1, I_br1, I_att1, I_We1, I_bias1;
    int I_Wfc, I_bfc, I_Wres, I_bres, I_Wtime, I_btime;
    if (in_sizes[0] == 2) {
        I_Wet = 0; I_Wfc = 1; I_Wres = 2; I_Wtime = 3; I_Wua = 4; I_Wuw = 5;
        I_We0 = 6; I_We1 = 7; I_Wl0 = 8; I_Wl1 = 9; I_Wr0 = 10; I_Wr1 = 11;
        I_att0 = 12; I_att1 = 13;
        I_bet = 14; I_bfc = 15; I_bres = 16; I_btime = 17; I_bua = 18; I_buw = 19;
        I_b = 20; I_bias0 = 21; I_bias1 = 22;
        I_bl0 = 23; I_bl1 = 24; I_br0 = 25; I_br1 = 26;
        I_ea = 27; I_ei = 28; I_x = 29;
    } else if (in_sizes[2] == 2 * EE) {
        I_x = 0; I_ea = 1; I_ei = 2; I_b = 3;
        I_Wet = 4; I_bet = 5; I_Wuw = 6; I_buw = 7; I_Wua = 8; I_bua = 9;
        I_Wl0 = 10; I_bl0 = 11; I_Wr0 = 12; I_br0 = 13; I_att0 = 14; I_We0 = 15; I_bias0 = 16;
        I_Wl1 = 17; I_bl1 = 18; I_Wr1 = 19; I_br1 = 20; I_att1 = 21; I_We1 = 22; I_bias1 = 23;
        I_Wfc = 24; I_bfc = 25; I_Wres = 26; I_bres = 27; I_Wtime = 28; I_btime = 29;
    } else {
        I_x = 0; I_ea = 1;
        I_Wet = 2; I_bet = 3; I_Wuw = 4; I_buw = 5; I_Wua = 6; I_bua = 7;
        I_Wl0 = 8; I_bl0 = 9; I_Wr0 = 10; I_br0 = 11; I_att0 = 12; I_We0 = 13; I_bias0 = 14;
        I_Wl1 = 15; I_bl1 = 16; I_Wr1 = 17; I_br1 = 18; I_att1 = 19; I_We1 = 20; I_bias1 = 21;
        I_Wfc = 22; I_bfc = 23; I_Wres = 24; I_bres = 25; I_Wtime = 26; I_btime = 27;
        I_ei = 28; I_b = 29;
    }

    const float* x        = (const float*)d_in[I_x];
    const float* edge_attr= (const float*)d_in[I_ea];
    const int*   edge_idx = (const int*)  d_in[I_ei];
    const int*   batch    = (const int*)  d_in[I_b];
    const float* W_et = (const float*)d_in[I_Wet], *b_et = (const float*)d_in[I_bet];
    const float* W_uw = (const float*)d_in[I_Wuw], *b_uw = (const float*)d_in[I_buw];
    const float* W_ua = (const float*)d_in[I_Wua], *b_ua = (const float*)d_in[I_bua];
    const float* Wl0 = (const float*)d_in[I_Wl0], *bl0 = (const float*)d_in[I_bl0];
    const float* Wr0 = (const float*)d_in[I_Wr0], *br0 = (const float*)d_in[I_br0];
    const float* att0 = (const float*)d_in[I_att0], *We0 = (const float*)d_in[I_We0];
    const float* bias0 = (const float*)d_in[I_bias0];
    const float* Wl1 = (const float*)d_in[I_Wl1], *bl1 = (const float*)d_in[I_bl1];
    const float* Wr1 = (const float*)d_in[I_Wr1], *br1 = (const float*)d_in[I_br1];
    const float* att1 = (const float*)d_in[I_att1], *We1 = (const float*)d_in[I_We1];
    const float* bias1 = (const float*)d_in[I_bias1];
    const float* W_fc = (const float*)d_in[I_Wfc], *b_fc = (const float*)d_in[I_bfc];
    const float* W_res = (const float*)d_in[I_Wres], *b_res = (const float*)d_in[I_bres];
    const float* W_time = (const float*)d_in[I_Wtime], *b_time = (const float*)d_in[I_btime];
    float* out = (float*)d_out;

    // launch order: position 4 is the ncu-profiled launch -> edge_kernel layer 0.
    hist_kernel<<<(EE + 255) / 256, 256>>>(edge_idx);                 // 1
    gemm_scan_kernel<<<NN / 16 + 1, 256>>>(x, Wl0, bl0, Wr0, br0);    // 2 (GEMM0 + scan)
    scatter_kernel<<<(EE + 255) / 256, 256>>>(edge_idx, edge_attr,    // 3
                                              W_et, b_et, W_uw, b_uw, W_ua, b_ua);
    edge_kernel<<<EDGE_BLOCKS, 256>>>(att0, We0, bias0);              // 4  <- profiled
    gemm_f2_kernel1<<<NN / 16, 256>>>(Wl1, bl1, Wr1, br1);            // 5
    edge_kernel<<<EDGE_BLOCKS, 256>>>(att1, We1, bias1);              // 6
    pool_kernel<<<(NN * HID + 255) / 256, 256>>>(batch);              // 7
    final_kernel<<<GG, 64>>>(W_fc, b_fc, W_res, b_res, W_time, b_time, out); // 8
    cleanup_kernel<<<128, 256>>>();                                   // 9
}

// round 16
// speedup vs baseline: 1.8369x; 1.0413x over previous
#include <cuda_runtime.h>
#include <cuda_bf16.h>
#include <cstdint>
#include <math.h>

// Problem constants
#define NN 50000
#define EE 400000
#define GG 64
#define IN_CH 128
#define HID 64
#define NHEAD 4
#define CH256 256   // NHEAD*HID
#define EDGE_BLOCKS 296                 // 2 CTAs/SM x 148 SMs: one persistent wave

typedef unsigned long long ull;

// ---------------- scratch (static __device__ globals; no allocation) ----------
__device__ __align__(16) float  g_xl[NN * CH256];     // 51.2 MB
__device__ __align__(16) float  g_xr[NN * CH256];     // 51.2 MB
__device__ __align__(16) float  g_h [NN * HID];       // 12.8 MB
__device__ __align__(16) int    g_hist[NN];
__device__ __align__(16) int    g_off [NN + 4];
__device__ __align__(16) int    g_cur [NN + 4];
__device__ __align__(16) int    g_csr_src[EE];
__device__ __align__(16) float4 g_csr_eap[EE];
__device__ __align__(16) float  g_pool[GG * HID];
__device__ __align__(16) float  g_cnt [GG];

// ---------------- packed f32x2 helpers ------------------------------------------
#define FFMA2(d, a, b) \
    asm("fma.rn.f32x2 %0, %1, %2, %0;" : "+l"(d) : "l"(a), "l"(b))
#define FFMA2D(d, a, b, c) \
    asm("fma.rn.f32x2 %0, %1, %2, %3;" : "=l"(d) : "l"(a), "l"(b), "l"(c))
#define ADD2(d, a, b) \
    asm("add.rn.f32x2 %0, %1, %2;" : "=l"(d) : "l"(a), "l"(b))
#define MUL2(d, a, b) \
    asm("mul.rn.f32x2 %0, %1, %2;" : "=l"(d) : "l"(a), "l"(b))
#define DUP2(d, f) \
    asm("mov.b64 %0, {%1, %1};" : "=l"(d) : "f"(f))
__device__ __forceinline__ float f2lo(ull v) { return __uint_as_float((uint32_t)v); }
__device__ __forceinline__ float f2hi(ull v) { return __uint_as_float((uint32_t)(v >> 32)); }

// ---------------- histogram of dst ---------------------------------------------
__global__ void hist_kernel(const int* __restrict__ edge_index) {
    int e = blockIdx.x * blockDim.x + threadIdx.x;
    if (e < EE) atomicAdd(&g_hist[edge_index[EE + e]], 1);
}

// ---------------- 256-thread block scan ------------------------------------------
__device__ void scan_block256() {
    __shared__ __align__(16) int wsum[8];
    __shared__ int s_carry;
    int t = threadIdx.x, lane = t & 31, wid = t >> 5;
    if (t == 0) s_carry = 0;
    __syncthreads();
    for (int base = 0; base < NN; base += 2048) {
        int i0 = base + t * 8;
        int v[8];
        if (i0 + 8 <= NN) {
            int4 a = *(const int4*)(g_hist + i0);
            int4 b = *(const int4*)(g_hist + i0 + 4);
            v[0]=a.x; v[1]=a.y; v[2]=a.z; v[3]=a.w;
            v[4]=b.x; v[5]=b.y; v[6]=b.z; v[7]=b.w;
        } else {
            #pragma unroll
            for (int j = 0; j < 8; j++) v[j] = (i0 + j < NN) ? g_hist[i0 + j] : 0;
        }
        int pre[8]; int s = 0;
        #pragma unroll
        for (int j = 0; j < 8; j++) { pre[j] = s; s += v[j]; }
        int x = s;
        #pragma unroll
        for (int o = 1; o < 32; o <<= 1) {
            int y = __shfl_up_sync(0xffffffffu, x, o);
            if (lane >= o) x += y;
        }
        if (lane == 31) wsum[wid] = x;
        __syncthreads();
        if (t == 0) {
            int c = s_carry;
            #pragma unroll
            for (int w8 = 0; w8 < 8; w8++) { int tmp = wsum[w8]; wsum[w8] = c; c += tmp; }
            s_carry = c;
        }
        __syncthreads();
        int toff = wsum[wid] + (x - s);
        #pragma unroll
        for (int j = 0; j < 8; j++) {
            int i = i0 + j;
            if (i < NN) { int e = toff + pre[j]; g_off[i] = e; g_cur[i] = e; }
        }
        __syncthreads();
    }
    if (t == 0) g_off[NN] = s_carry;
}

// ---------------- FFMA2 GEMM body ------------------------------------------------
template <int K, bool USE_GH>
__device__ __forceinline__ void gemm_body(int bx,
        const float* __restrict__ x,
        const float* __restrict__ Wl, const float* __restrict__ bl,
        const float* __restrict__ Wr, const float* __restrict__ br,
        float* xsT) {
    int t = threadIdx.x;
    int node0 = bx * 16;
    const float* __restrict__ src = USE_GH ? (const float*)g_h : x;
    for (int i = t; i < 16 * K; i += 256) {
        int n = i / K, k = i % K;
        xsT[k * 20 + n] = src[(size_t)(node0 + n) * K + k];
    }
    __syncthreads();

    ull accl[8], accr[8];
    #pragma unroll
    for (int p = 0; p < 8; p++) { accl[p] = 0ull; accr[p] = 0ull; }

    #pragma unroll 2
    for (int k = 0; k < K; k++) {
        const ulonglong2* rp = (const ulonglong2*)(xsT + k * 20);
        ulonglong2 q0 = rp[0], q1 = rp[1], q2 = rp[2], q3 = rp[3];
        float wl = __ldg(&Wl[k * CH256 + t]);
        float wr = __ldg(&Wr[k * CH256 + t]);
        ull wld, wrd;
        DUP2(wld, wl); DUP2(wrd, wr);
        FFMA2(accl[0], q0.x, wld); FFMA2(accl[1], q0.y, wld);
        FFMA2(accl[2], q1.x, wld); FFMA2(accl[3], q1.y, wld);
        FFMA2(accl[4], q2.x, wld); FFMA2(accl[5], q2.y, wld);
        FFMA2(accl[6], q3.x, wld); FFMA2(accl[7], q3.y, wld);
        FFMA2(accr[0], q0.x, wrd); FFMA2(accr[1], q0.y, wrd);
        FFMA2(accr[2], q1.x, wrd); FFMA2(accr[3], q1.y, wrd);
        FFMA2(accr[4], q2.x, wrd); FFMA2(accr[5], q2.y, wrd);
        FFMA2(accr[6], q3.x, wrd); FFMA2(accr[7], q3.y, wrd);
    }

    float bbl = bl[t], bbr = br[t];
    #pragma unroll
    for (int p = 0; p < 8; p++) {
        size_t n = node0 + 2 * p;
        g_xl[n * CH256 + t]       = f2lo(accl[p]) + bbl;
        g_xl[(n + 1) * CH256 + t] = f2hi(accl[p]) + bbl;
        g_xr[n * CH256 + t]       = f2lo(accr[p]) + bbr;
        g_xr[(n + 1) * CH256 + t] = f2hi(accr[p]) + bbr;
    }
}

// layer-0 GEMM fused with the CSR scan: block 0 scans, blocks 1.. do GEMM.
__global__ __launch_bounds__(256) void gemm_scan_kernel(
        const float* __restrict__ x,
        const float* __restrict__ Wl, const float* __restrict__ bl,
        const float* __restrict__ Wr, const float* __restrict__ br) {
    __shared__ __align__(16) float xsT[IN_CH * 20];
    if (blockIdx.x == 0) { scan_block256(); return; }
    gemm_body<IN_CH, false>(blockIdx.x - 1, x, Wl, bl, Wr, br, xsT);
}

__global__ __launch_bounds__(256) void gemm_f2_kernel1(
        const float* __restrict__ Wl, const float* __restrict__ bl,
        const float* __restrict__ Wr, const float* __restrict__ br) {
    __shared__ __align__(16) float xsT[HID * 20];
    gemm_body<HID, true>(blockIdx.x, nullptr, Wl, bl, Wr, br, xsT);
}

// ---------------- scatter edges into CSR + edge-attr projection ---------------
__global__ void scatter_kernel(const int* __restrict__ edge_index,
                               const float* __restrict__ edge_attr,
                               const float* __restrict__ W_et, const float* __restrict__ b_et,
                               const float* __restrict__ W_uw, const float* __restrict__ b_uw,
                               const float* __restrict__ W_ua, const float* __restrict__ b_ua) {
    int e = blockIdx.x * blockDim.x + threadIdx.x;
    if (e >= EE) return;
    int s = edge_index[e];
    int d = edge_index[EE + e];
    int pos = atomicAdd(&g_cur[d], 1);
    g_csr_src[pos] = s;
    float et = edge_attr[2 * e];
    float uw = edge_attr[2 * e + 1];
    float ua = 1.f / (1.f + __expf(-(uw * W_ua[0] + b_ua[0])));
    float4 ep;
    ep.x = et * W_et[0] + b_et[0];
    ep.y = et * W_et[1] + b_et[1];
    ep.z = (uw * W_uw[0] + b_uw[0]) * ua;
    ep.w = (uw * W_uw[1] + b_uw[1]) * ua;
    g_csr_eap[pos] = ep;
}

// ---------------- persistent warp-per-node edge stage, pair-processed -----------
// Edges consumed two at a time; the NEXT pair's xl rows prefetch while the
// current pair computes (4 gathers in flight/warp). Score chains of the two
// edges interleave (SHFL/MUFU latency overlap). Summation order per node is
// identical to the sequential version.
__global__ __launch_bounds__(256, 2) void edge_kernel(
        const float* __restrict__ att, const float* __restrict__ We,
        const float* __restrict__ bias) {
    int t = threadIdx.x;
    int w = t >> 5, lane = t & 31;
    int cb = 8 * lane;
    int gw = blockIdx.x * 8 + w;
    const int NW = EDGE_BLOCKS * 8;

    ull we0p[4], we1p[4], we2p[4], we3p[4], avp[4];
    {
        const ulonglong2* p;
        ulonglong2 a, b;
        p = (const ulonglong2*)(We + 0 * CH256 + cb); a = p[0]; b = p[1];
        we0p[0]=a.x; we0p[1]=a.y; we0p[2]=b.x; we0p[3]=b.y;
        p = (const ulonglong2*)(We + 1 * CH256 + cb); a = p[0]; b = p[1];
        we1p[0]=a.x; we1p[1]=a.y; we1p[2]=b.x; we1p[3]=b.y;
        p = (const ulonglong2*)(We + 2 * CH256 + cb); a = p[0]; b = p[1];
        we2p[0]=a.x; we2p[1]=a.y; we2p[2]=b.x; we2p[3]=b.y;
        p = (const ulonglong2*)(We + 3 * CH256 + cb); a = p[0]; b = p[1];
        we3p[0]=a.x; we3p[1]=a.y; we3p[2]=b.x; we3p[3]=b.y;
        p = (const ulonglong2*)(att + cb); a = p[0]; b = p[1];
        avp[0]=a.x; avp[1]=a.y; avp[2]=b.x; avp[3]=b.y;
    }
    ull c06, c04;
    DUP2(c06, 0.6f); DUP2(c04, 0.4f);
    float4 bv0, bv1;
    if (lane < 8) {
        bv0 = *(const float4*)(bias + 8 * lane);
        bv1 = *(const float4*)(bias + 8 * lane + 4);
    }

    for (int n = gw; n < NN; n += NW) {
        ull xrp[4];
        {
            const ulonglong2* p = (const ulonglong2*)(g_xr + (size_t)n * CH256 + cb);
            ulonglong2 a = p[0], b = p[1];
            xrp[0]=a.x; xrp[1]=a.y; xrp[2]=b.x; xrp[3]=b.y;
        }
        ull acc[4] = {0ull, 0ull, 0ull, 0ull};
        float den = 0.f;
        int e0 = g_off[n], e1 = g_off[n + 1];
        int e = e0;

        // warm-up: load current pair's xl rows
        ull xA[4] = {0,0,0,0}, xB[4] = {0,0,0,0};
        if (e < e1) {
            int sA = __ldg(&g_csr_src[e]);
            const ulonglong2* p = (const ulonglong2*)(g_xl + (size_t)sA * CH256 + cb);
            ulonglong2 a = p[0], b = p[1];
            xA[0]=a.x; xA[1]=a.y; xA[2]=b.x; xA[3]=b.y;
        }
        if (e + 1 < e1) {
            int sB = __ldg(&g_csr_src[e + 1]);
            const ulonglong2* p = (const ulonglong2*)(g_xl + (size_t)sB * CH256 + cb);
            ulonglong2 a = p[0], b = p[1];
            xB[0]=a.x; xB[1]=a.y; xB[2]=b.x; xB[3]=b.y;
        }

        while (e < e1) {
            bool hasB = (e + 1 < e1);
            // prefetch NEXT pair's xl rows (MLP=4 with the 2 rows in flight above)
            ull xA2[4] = {xA[0],xA[1],xA[2],xA[3]}, xB2[4] = {xB[0],xB[1],xB[2],xB[3]};
            if (e + 2 < e1) {
                int sA2 = __ldg(&g_csr_src[e + 2]);
                const ulonglong2* p = (const ulonglong2*)(g_xl + (size_t)sA2 * CH256 + cb);
                ulonglong2 a = p[0], b = p[1];
                xA2[0]=a.x; xA2[1]=a.y; xA2[2]=b.x; xA2[3]=b.y;
            }
            if (e + 3 < e1) {
                int sB2 = __ldg(&g_csr_src[e + 3]);
                const ulonglong2* p = (const ulonglong2*)(g_xl + (size_t)sB2 * CH256 + cb);
                ulonglong2 a = p[0], b = p[1];
                xB2[0]=a.x; xB2[1]=a.y; xB2[2]=b.x; xB2[3]=b.y;
            }
            // eap loads (line-local, L1/L2-hot)
            float4 epA = g_csr_eap[e];
            float4 epB = hasB ? g_csr_eap[e + 1] : epA;

            ull eAx, eAy, eAz, eAw, eBx, eBy, eBz, eBw;
            DUP2(eAx, epA.x); DUP2(eAy, epA.y); DUP2(eAz, epA.z); DUP2(eAw, epA.w);
            DUP2(eBx, epB.x); DUP2(eBy, epB.y); DUP2(eBz, epB.z); DUP2(eBw, epB.w);
            ull pA2 = 0ull, pB2 = 0ull;
            #pragma unroll
            for (int i = 0; i < 4; i++) {
                ull eeA, eeB;
                FFMA2D(eeA, eAx, we0p[i], xrp[i]);
                FFMA2D(eeB, eBx, we0p[i], xrp[i]);
                FFMA2(eeA, eAy, we1p[i]);  FFMA2(eeB, eBy, we1p[i]);
                FFMA2(eeA, eAz, we2p[i]);  FFMA2(eeB, eBz, we2p[i]);
                FFMA2(eeA, eAw, we3p[i]);  FFMA2(eeB, eBw, we3p[i]);
                ull mA, mB;
                ADD2(mA, xA[i], eeA);      ADD2(mB, xB[i], eeB);
                ull aA = mA & 0x7FFFFFFF7FFFFFFFull;
                ull aB = mB & 0x7FFFFFFF7FFFFFFFull;
                ull lA, lB;
                MUL2(lA, mA, c06);         MUL2(lB, mB, c06);
                FFMA2D(lA, aA, c04, lA);   FFMA2D(lB, aB, c04, lB);
                FFMA2(pA2, lA, avp[i]);    FFMA2(pB2, lB, avp[i]);
            }
            float pA = f2lo(pA2) + f2hi(pA2);
            float pB = f2lo(pB2) + f2hi(pB2);
            // interleaved oct reduces (latency overlap)
            pA += __shfl_xor_sync(0xffffffffu, pA, 1);
            pB += __shfl_xor_sync(0xffffffffu, pB, 1);
            pA += __shfl_xor_sync(0xffffffffu, pA, 2);
            pB += __shfl_xor_sync(0xffffffffu, pB, 2);
            pA += __shfl_xor_sync(0xffffffffu, pA, 4);
            pB += __shfl_xor_sync(0xffffffffu, pB, 4);
            float exA = __expf(pA);
            float exB = __expf(pB);
            // sequential-order accumulation: edge e first, then e+1
            den += exA;
            ull dA; DUP2(dA, exA);
            #pragma unroll
            for (int i = 0; i < 4; i++) FFMA2(acc[i], xA[i], dA);
            if (hasB) {
                den += exB;
                ull dB; DUP2(dB, exB);
                #pragma unroll
                for (int i = 0; i < 4; i++) FFMA2(acc[i], xB[i], dB);
            }
            #pragma unroll
            for (int i = 0; i < 4; i++) { xA[i] = xA2[i]; xB[i] = xB2[i]; }
            e += 2;
        }

        float inv = 1.f / (den + 1e-16f);
        float a8[8];
        #pragma unroll
        for (int i = 0; i < 4; i++) {
            a8[2*i]   = f2lo(acc[i]) * inv;
            a8[2*i+1] = f2hi(acc[i]) * inv;
        }
        #pragma unroll
        for (int j = 0; j < 8; j++) {
            float v = a8[j];
            v += __shfl_xor_sync(0xffffffffu, v, 8);
            v += __shfl_xor_sync(0xffffffffu, v, 16);
            a8[j] = v;
        }
        if (lane < 8) {
            float o0 = fmaxf(a8[0] * 0.25f + bv0.x, 0.f);
            float o1 = fmaxf(a8[1] * 0.25f + bv0.y, 0.f);
            float o2 = fmaxf(a8[2] * 0.25f + bv0.z, 0.f);
            float o3 = fmaxf(a8[3] * 0.25f + bv0.w, 0.f);
            float o4 = fmaxf(a8[4] * 0.25f + bv1.x, 0.f);
            float o5 = fmaxf(a8[5] * 0.25f + bv1.y, 0.f);
            float o6 = fmaxf(a8[6] * 0.25f + bv1.z, 0.f);
            float o7 = fmaxf(a8[7] * 0.25f + bv1.w, 0.f);
            float* hp = g_h + (size_t)n * HID + 8 * lane;
            *(float4*)hp       = make_float4(o0, o1, o2, o3);
            *(float4*)(hp + 4) = make_float4(o4, o5, o6, o7);
        }
    }
}

// ---------------- graph pooling -------------------------------------------------
__global__ void pool_kernel(const int* __restrict__ batch) {
    int idx = blockIdx.x * blockDim.x + threadIdx.x;
    if (idx >= NN * HID) return;
    int n = idx >> 6, c = idx & 63;
    int g = batch[n];
    atomicAdd(&g_pool[g * HID + c], g_h[idx]);
    if (c == 0) atomicAdd(&g_cnt[g], 1.f);
}

// ---------------- head ----------------------------------------------------------
__global__ __launch_bounds__(64) void final_kernel(
        const float* __restrict__ W_fc, const float* __restrict__ b_fc,
        const float* __restrict__ W_res, const float* __restrict__ b_res,
        const float* __restrict__ W_time, const float* __restrict__ b_time,
        float* __restrict__ out) {
    int g = blockIdx.x;
    int c = threadIdx.x;
    float inv = 1.f / fmaxf(g_cnt[g], 1.f);
    float acc = b_fc[c];
    for (int k = 0; k < HID; k++)
        acc = fmaf(g_pool[g * HID + k] * inv, W_fc[k * HID + c], acc);
    float gv = (acc > 0.f) ? acc : 0.f;
    float r  = gv * W_res[c];
    float tm = gv * W_time[c];
    #pragma unroll
    for (int o = 16; o; o >>= 1) {
        r  += __shfl_xor_sync(0xffffffffu, r, o);
        tm += __shfl_xor_sync(0xffffffffu, tm, o);
    }
    __shared__ float sr[2], st[2];
    if ((c & 31) == 0) { sr[c >> 5] = r; st[c >> 5] = tm; }
    __syncthreads();
    if (c == 0) {
        out[g * 2 + 0] = sr[0] + sr[1] + b_res[0];
        out[g * 2 + 1] = st[0] + st[1] + b_time[0];
    }
}

// ---------------- cleanup: restore zeroed state for the next replay -------------
__global__ void cleanup_kernel() {
    int idx = blockIdx.x * blockDim.x + threadIdx.x;
    int stride = gridDim.x * blockDim.x;
    for (int i = idx; i < NN; i += stride) g_hist[i] = 0;
    for (int i = idx; i < GG * HID; i += stride) g_pool[i] = 0.f;
    for (int i = idx; i < GG; i += stride) g_cnt[i] = 0.f;
}

// ---------------- launcher -------------------------------------------------------
extern "C" void kernel_launch(void* const* d_in, const int* in_sizes, int n_in,
                              void* d_out, int out_size) {
    int I_x, I_ea, I_ei, I_b, I_Wet, I_bet, I_Wuw, I_buw, I_Wua, I_bua;
    int I_Wl0, I_bl0, I_Wr0, I_br0, I_att0, I_We0, I_bias0;
    int I_Wl1, I_bl1, I_Wr1, I_br1, I_att1, I_We1, I_bias1;
    int I_Wfc, I_bfc, I_Wres, I_bres, I_Wtime, I_btime;
    if (in_sizes[0] == 2) {
        I_Wet = 0; I_Wfc = 1; I_Wres = 2; I_Wtime = 3; I_Wua = 4; I_Wuw = 5;
        I_We0 = 6; I_We1 = 7; I_Wl0 = 8; I_Wl1 = 9; I_Wr0 = 10; I_Wr1 = 11;
        I_att0 = 12; I_att1 = 13;
        I_bet = 14; I_bfc = 15; I_bres = 16; I_btime = 17; I_bua = 18; I_buw = 19;
        I_b = 20; I_bias0 = 21; I_bias1 = 22;
        I_bl0 = 23; I_bl1 = 24; I_br0 = 25; I_br1 = 26;
        I_ea = 27; I_ei = 28; I_x = 29;
    } else if (in_sizes[2] == 2 * EE) {
        I_x = 0; I_ea = 1; I_ei = 2; I_b = 3;
        I_Wet = 4; I_bet = 5; I_Wuw = 6; I_buw = 7; I_Wua = 8; I_bua = 9;
        I_Wl0 = 10; I_bl0 = 11; I_Wr0 = 12; I_br0 = 13; I_att0 = 14; I_We0 = 15; I_bias0 = 16;
        I_Wl1 = 17; I_bl1 = 18; I_Wr1 = 19; I_br1 = 20; I_att1 = 21; I_We1 = 22; I_bias1 = 23;
        I_Wfc = 24; I_bfc = 25; I_Wres = 26; I_bres = 27; I_Wtime = 28; I_btime = 29;
    } else {
        I_x = 0; I_ea = 1;
        I_Wet = 2; I_bet = 3; I_Wuw = 4; I_buw = 5; I_Wua = 6; I_bua = 7;
        I_Wl0 = 8; I_bl0 = 9; I_Wr0 = 10; I_br0 = 11; I_att0 = 12; I_We0 = 13; I_bias0 = 14;
        I_Wl1 = 15; I_bl1 = 16; I_Wr1 = 17; I_br1 = 18; I_att1 = 19; I_We1 = 20; I_bias1 = 21;
        I_Wfc = 22; I_bfc = 23; I_Wres = 24; I_bres = 25; I_Wtime = 26; I_btime = 27;
        I_ei = 28; I_b = 29;
    }

    const float* x        = (const float*)d_in[I_x];
    const float* edge_attr= (const float*)d_in[I_ea];
    const int*   edge_idx = (const int*)  d_in[I_ei];
    const int*   batch    = (const int*)  d_in[I_b];
    const float* W_et = (const float*)d_in[I_Wet], *b_et = (const float*)d_in[I_bet];
    const float* W_uw = (const float*)d_in[I_Wuw], *b_uw = (const float*)d_in[I_buw];
    const float* W_ua = (const float*)d_in[I_Wua], *b_ua = (const float*)d_in[I_bua];
    const float* Wl0 = (const float*)d_in[I_Wl0], *bl0 = (const float*)d_in[I_bl0];
    const float* Wr0 = (const float*)d_in[I_Wr0], *br0 = (const float*)d_in[I_br0];
    const float* att0 = (const float*)d_in[I_att0], *We0 = (const float*)d_in[I_We0];
    const float* bias0 = (const float*)d_in[I_bias0];
    const float* Wl1 = (const float*)d_in[I_Wl1], *bl1 = (const float*)d_in[I_bl1];
    const float* Wr1 = (const float*)d_in[I_Wr1], *br1 = (const float*)d_in[I_br1];
    const float* att1 = (const float*)d_in[I_att1], *We1 = (const float*)d_in[I_We1];
    const float* bias1 = (const float*)d_in[I_bias1];
    const float* W_fc = (const float*)d_in[I_Wfc], *b_fc = (const float*)d_in[I_bfc];
    const float* W_res = (const float*)d_in[I_Wres], *b_res = (const float*)d_in[I_bres];
    const float* W_time = (const float*)d_in[I_Wtime], *b_time = (const float*)d_in[I_btime];
    float* out = (float*)d_out;

    // launch order: position 4 is the ncu-profiled launch -> edge_kernel layer 0.
    hist_kernel<<<(EE + 255) / 256, 256>>>(edge_idx);                 // 1
    gemm_scan_kernel<<<NN / 16 + 1, 256>>>(x, Wl0, bl0, Wr0, br0);    // 2 (GEMM0 + scan)
    scatter_kernel<<<(EE + 255) / 256, 256>>>(edge_idx, edge_attr,    // 3
                                              W_et, b_et, W_uw, b_uw, W_ua, b_ua);
    edge_kernel<<<EDGE_BLOCKS, 256>>>(att0, We0, bias0);              // 4  <- profiled
    gemm_f2_kernel1<<<NN / 16, 256>>>(Wl1, bl1, Wr1, br1);            // 5
    edge_kernel<<<EDGE_BLOCKS, 256>>>(att1, We1, bias1);              // 6
    pool_kernel<<<(NN * HID + 255) / 256, 256>>>(batch);              // 7
    final_kernel<<<GG, 64>>>(W_fc, b_fc, W_res, b_res, W_time, b_time, out); // 8
    cleanup_kernel<<<128, 256>>>();                                   // 9
}

// round 17
// speedup vs baseline: 1.9222x; 1.0464x over previous
#include <cuda_runtime.h>
#include <cuda_bf16.h>
#include <cuda_fp16.h>
#include <cstdint>
#include <math.h>

// Problem constants
#define NN 50000
#define EE 400000
#define GG 64
#define IN_CH 128
#define HID 64
#define NHEAD 4
#define CH256 256   // NHEAD*HID
#define EDGE_BLOCKS 296                 // 2 CTAs/SM x 148 SMs: one persistent wave

typedef unsigned long long ull;

// ---------------- scratch (static __device__ globals; no allocation) ----------
__device__ __align__(16) __half g_xlh[NN * CH256];    // 25.6 MB (gathered -> fp16)
__device__ __align__(16) float  g_xr[NN * CH256];     // 51.2 MB
__device__ __align__(16) float  g_h [NN * HID];       // 12.8 MB
__device__ __align__(16) int    g_hist[NN];
__device__ __align__(16) int    g_off [NN + 4];
__device__ __align__(16) int    g_cur [NN + 4];
__device__ __align__(16) int    g_csr_src[EE];
__device__ __align__(16) float4 g_csr_eap[EE];
__device__ __align__(16) float  g_pool[GG * HID];
__device__ __align__(16) float  g_cnt [GG];

// ---------------- packed f32x2 helpers ------------------------------------------
#define FFMA2(d, a, b) \
    asm("fma.rn.f32x2 %0, %1, %2, %0;" : "+l"(d) : "l"(a), "l"(b))
#define FFMA2D(d, a, b, c) \
    asm("fma.rn.f32x2 %0, %1, %2, %3;" : "=l"(d) : "l"(a), "l"(b), "l"(c))
#define ADD2(d, a, b) \
    asm("add.rn.f32x2 %0, %1, %2;" : "=l"(d) : "l"(a), "l"(b))
#define MUL2(d, a, b) \
    asm("mul.rn.f32x2 %0, %1, %2;" : "=l"(d) : "l"(a), "l"(b))
#define DUP2(d, f) \
    asm("mov.b64 %0, {%1, %1};" : "=l"(d) : "f"(f))
#define PACK2(d, lo, hi) \
    asm("mov.b64 %0, {%1, %2};" : "=l"(d) : "f"(lo), "f"(hi))
__device__ __forceinline__ float f2lo(ull v) { return __uint_as_float((uint32_t)v); }
__device__ __forceinline__ float f2hi(ull v) { return __uint_as_float((uint32_t)(v >> 32)); }

// convert 8 packed halves (uint4) -> 4 packed f32x2
__device__ __forceinline__ void h8_to_f2x4(uint4 h, ull* x) {
    float2 f0 = __half22float2(*reinterpret_cast<__half2*>(&h.x));
    float2 f1 = __half22float2(*reinterpret_cast<__half2*>(&h.y));
    float2 f2 = __half22float2(*reinterpret_cast<__half2*>(&h.z));
    float2 f3 = __half22float2(*reinterpret_cast<__half2*>(&h.w));
    PACK2(x[0], f0.x, f0.y);
    PACK2(x[1], f1.x, f1.y);
    PACK2(x[2], f2.x, f2.y);
    PACK2(x[3], f3.x, f3.y);
}

// ---------------- histogram of dst ---------------------------------------------
__global__ void hist_kernel(const int* __restrict__ edge_index) {
    int e = blockIdx.x * blockDim.x + threadIdx.x;
    if (e < EE) atomicAdd(&g_hist[edge_index[EE + e]], 1);
}

// ---------------- 256-thread block scan ------------------------------------------
__device__ void scan_block256() {
    __shared__ __align__(16) int wsum[8];
    __shared__ int s_carry;
    int t = threadIdx.x, lane = t & 31, wid = t >> 5;
    if (t == 0) s_carry = 0;
    __syncthreads();
    for (int base = 0; base < NN; base += 2048) {
        int i0 = base + t * 8;
        int v[8];
        if (i0 + 8 <= NN) {
            int4 a = *(const int4*)(g_hist + i0);
            int4 b = *(const int4*)(g_hist + i0 + 4);
            v[0]=a.x; v[1]=a.y; v[2]=a.z; v[3]=a.w;
            v[4]=b.x; v[5]=b.y; v[6]=b.z; v[7]=b.w;
        } else {
            #pragma unroll
            for (int j = 0; j < 8; j++) v[j] = (i0 + j < NN) ? g_hist[i0 + j] : 0;
        }
        int pre[8]; int s = 0;
        #pragma unroll
        for (int j = 0; j < 8; j++) { pre[j] = s; s += v[j]; }
        int x = s;
        #pragma unroll
        for (int o = 1; o < 32; o <<= 1) {
            int y = __shfl_up_sync(0xffffffffu, x, o);
            if (lane >= o) x += y;
        }
        if (lane == 31) wsum[wid] = x;
        __syncthreads();
        if (t == 0) {
            int c = s_carry;
            #pragma unroll
            for (int w8 = 0; w8 < 8; w8++) { int tmp = wsum[w8]; wsum[w8] = c; c += tmp; }
            s_carry = c;
        }
        __syncthreads();
        int toff = wsum[wid] + (x - s);
        #pragma unroll
        for (int j = 0; j < 8; j++) {
            int i = i0 + j;
            if (i < NN) { int e = toff + pre[j]; g_off[i] = e; g_cur[i] = e; }
        }
        __syncthreads();
    }
    if (t == 0) g_off[NN] = s_carry;
}

// ---------------- FFMA2 GEMM body (xl written as fp16) --------------------------
template <int K, bool USE_GH>
__device__ __forceinline__ void gemm_body(int bx,
        const float* __restrict__ x,
        const float* __restrict__ Wl, const float* __restrict__ bl,
        const float* __restrict__ Wr, const float* __restrict__ br,
        float* xsT) {
    int t = threadIdx.x;
    int node0 = bx * 16;
    const float* __restrict__ src = USE_GH ? (const float*)g_h : x;
    for (int i = t; i < 16 * K; i += 256) {
        int n = i / K, k = i % K;
        xsT[k * 20 + n] = src[(size_t)(node0 + n) * K + k];
    }
    __syncthreads();

    ull accl[8], accr[8];
    #pragma unroll
    for (int p = 0; p < 8; p++) { accl[p] = 0ull; accr[p] = 0ull; }

    #pragma unroll 2
    for (int k = 0; k < K; k++) {
        const ulonglong2* rp = (const ulonglong2*)(xsT + k * 20);
        ulonglong2 q0 = rp[0], q1 = rp[1], q2 = rp[2], q3 = rp[3];
        float wl = __ldg(&Wl[k * CH256 + t]);
        float wr = __ldg(&Wr[k * CH256 + t]);
        ull wld, wrd;
        DUP2(wld, wl); DUP2(wrd, wr);
        FFMA2(accl[0], q0.x, wld); FFMA2(accl[1], q0.y, wld);
        FFMA2(accl[2], q1.x, wld); FFMA2(accl[3], q1.y, wld);
        FFMA2(accl[4], q2.x, wld); FFMA2(accl[5], q2.y, wld);
        FFMA2(accl[6], q3.x, wld); FFMA2(accl[7], q3.y, wld);
        FFMA2(accr[0], q0.x, wrd); FFMA2(accr[1], q0.y, wrd);
        FFMA2(accr[2], q1.x, wrd); FFMA2(accr[3], q1.y, wrd);
        FFMA2(accr[4], q2.x, wrd); FFMA2(accr[5], q2.y, wrd);
        FFMA2(accr[6], q3.x, wrd); FFMA2(accr[7], q3.y, wrd);
    }

    float bbl = bl[t], bbr = br[t];
    #pragma unroll
    for (int p = 0; p < 8; p++) {
        size_t n = node0 + 2 * p;
        g_xlh[n * CH256 + t]       = __float2half_rn(f2lo(accl[p]) + bbl);
        g_xlh[(n + 1) * CH256 + t] = __float2half_rn(f2hi(accl[p]) + bbl);
        g_xr[n * CH256 + t]        = f2lo(accr[p]) + bbr;
        g_xr[(n + 1) * CH256 + t]  = f2hi(accr[p]) + bbr;
    }
}

// layer-0 GEMM fused with the CSR scan: block 0 scans, blocks 1.. do GEMM.
__global__ __launch_bounds__(256) void gemm_scan_kernel(
        const float* __restrict__ x,
        const float* __restrict__ Wl, const float* __restrict__ bl,
        const float* __restrict__ Wr, const float* __restrict__ br) {
    __shared__ __align__(16) float xsT[IN_CH * 20];
    if (blockIdx.x == 0) { scan_block256(); return; }
    gemm_body<IN_CH, false>(blockIdx.x - 1, x, Wl, bl, Wr, br, xsT);
}

__global__ __launch_bounds__(256) void gemm_f2_kernel1(
        const float* __restrict__ Wl, const float* __restrict__ bl,
        const float* __restrict__ Wr, const float* __restrict__ br) {
    __shared__ __align__(16) float xsT[HID * 20];
    gemm_body<HID, true>(blockIdx.x, nullptr, Wl, bl, Wr, br, xsT);
}

// ---------------- scatter edges into CSR + edge-attr projection ---------------
__global__ void scatter_kernel(const int* __restrict__ edge_index,
                               const float* __restrict__ edge_attr,
                               const float* __restrict__ W_et, const float* __restrict__ b_et,
                               const float* __restrict__ W_uw, const float* __restrict__ b_uw,
                               const float* __restrict__ W_ua, const float* __restrict__ b_ua) {
    int e = blockIdx.x * blockDim.x + threadIdx.x;
    if (e >= EE) return;
    int s = edge_index[e];
    int d = edge_index[EE + e];
    int pos = atomicAdd(&g_cur[d], 1);
    g_csr_src[pos] = s;
    float et = edge_attr[2 * e];
    float uw = edge_attr[2 * e + 1];
    float ua = 1.f / (1.f + __expf(-(uw * W_ua[0] + b_ua[0])));
    float4 ep;
    ep.x = et * W_et[0] + b_et[0];
    ep.y = et * W_et[1] + b_et[1];
    ep.z = (uw * W_uw[0] + b_uw[0]) * ua;
    ep.w = (uw * W_uw[1] + b_uw[1]) * ua;
    g_csr_eap[pos] = ep;
}

// ---------------- persistent warp-per-node edge stage ---------------------------
// Pair-processed with cross-pair prefetch (MLP=4). xl gathered as fp16 (uint4
// per lane, converted to packed f32x2 at compute time); all math fp32.
__global__ __launch_bounds__(256, 2) void edge_kernel(
        const float* __restrict__ att, const float* __restrict__ We,
        const float* __restrict__ bias) {
    int t = threadIdx.x;
    int w = t >> 5, lane = t & 31;
    int cb = 8 * lane;
    int gw = blockIdx.x * 8 + w;
    const int NW = EDGE_BLOCKS * 8;

    ull we0p[4], we1p[4], we2p[4], we3p[4], avp[4];
    {
        const ulonglong2* p;
        ulonglong2 a, b;
        p = (const ulonglong2*)(We + 0 * CH256 + cb); a = p[0]; b = p[1];
        we0p[0]=a.x; we0p[1]=a.y; we0p[2]=b.x; we0p[3]=b.y;
        p = (const ulonglong2*)(We + 1 * CH256 + cb); a = p[0]; b = p[1];
        we1p[0]=a.x; we1p[1]=a.y; we1p[2]=b.x; we1p[3]=b.y;
        p = (const ulonglong2*)(We + 2 * CH256 + cb); a = p[0]; b = p[1];
        we2p[0]=a.x; we2p[1]=a.y; we2p[2]=b.x; we2p[3]=b.y;
        p = (const ulonglong2*)(We + 3 * CH256 + cb); a = p[0]; b = p[1];
        we3p[0]=a.x; we3p[1]=a.y; we3p[2]=b.x; we3p[3]=b.y;
        p = (const ulonglong2*)(att + cb); a = p[0]; b = p[1];
        avp[0]=a.x; avp[1]=a.y; avp[2]=b.x; avp[3]=b.y;
    }
    ull c06, c04;
    DUP2(c06, 0.6f); DUP2(c04, 0.4f);
    float4 bv0, bv1;
    if (lane < 8) {
        bv0 = *(const float4*)(bias + 8 * lane);
        bv1 = *(const float4*)(bias + 8 * lane + 4);
    }

    for (int n = gw; n < NN; n += NW) {
        ull xrp[4];
        {
            const ulonglong2* p = (const ulonglong2*)(g_xr + (size_t)n * CH256 + cb);
            ulonglong2 a = p[0], b = p[1];
            xrp[0]=a.x; xrp[1]=a.y; xrp[2]=b.x; xrp[3]=b.y;
        }
        ull acc[4] = {0ull, 0ull, 0ull, 0ull};
        float den = 0.f;
        int e0 = g_off[n], e1 = g_off[n + 1];
        int e = e0;

        // warm-up: load current pair's fp16 xl rows (1 LDG.128 each)
        uint4 hA = make_uint4(0,0,0,0), hB = hA;
        if (e < e1) {
            int sA = __ldg(&g_csr_src[e]);
            hA = *(const uint4*)(g_xlh + (size_t)sA * CH256 + cb);
        }
        if (e + 1 < e1) {
            int sB = __ldg(&g_csr_src[e + 1]);
            hB = *(const uint4*)(g_xlh + (size_t)sB * CH256 + cb);
        }

        while (e < e1) {
            bool hasB = (e + 1 < e1);
            // prefetch NEXT pair's xl rows (4 gathers in flight per warp)
            uint4 hA2 = hA, hB2 = hB;
            if (e + 2 < e1) {
                int sA2 = __ldg(&g_csr_src[e + 2]);
                hA2 = *(const uint4*)(g_xlh + (size_t)sA2 * CH256 + cb);
            }
            if (e + 3 < e1) {
                int sB2 = __ldg(&g_csr_src[e + 3]);
                hB2 = *(const uint4*)(g_xlh + (size_t)sB2 * CH256 + cb);
            }
            float4 epA = g_csr_eap[e];
            float4 epB = hasB ? g_csr_eap[e + 1] : epA;

            ull xA[4], xB[4];
            h8_to_f2x4(hA, xA);
            h8_to_f2x4(hB, xB);

            ull eAx, eAy, eAz, eAw, eBx, eBy, eBz, eBw;
            DUP2(eAx, epA.x); DUP2(eAy, epA.y); DUP2(eAz, epA.z); DUP2(eAw, epA.w);
            DUP2(eBx, epB.x); DUP2(eBy, epB.y); DUP2(eBz, epB.z); DUP2(eBw, epB.w);
            ull pA2 = 0ull, pB2 = 0ull;
            #pragma unroll
            for (int i = 0; i < 4; i++) {
                ull eeA, eeB;
                FFMA2D(eeA, eAx, we0p[i], xrp[i]);
                FFMA2D(eeB, eBx, we0p[i], xrp[i]);
                FFMA2(eeA, eAy, we1p[i]);  FFMA2(eeB, eBy, we1p[i]);
                FFMA2(eeA, eAz, we2p[i]);  FFMA2(eeB, eBz, we2p[i]);
                FFMA2(eeA, eAw, we3p[i]);  FFMA2(eeB, eBw, we3p[i]);
                ull mA, mB;
                ADD2(mA, xA[i], eeA);      ADD2(mB, xB[i], eeB);
                ull aA = mA & 0x7FFFFFFF7FFFFFFFull;
                ull aB = mB & 0x7FFFFFFF7FFFFFFFull;
                ull lA, lB;
                MUL2(lA, mA, c06);         MUL2(lB, mB, c06);
                FFMA2D(lA, aA, c04, lA);   FFMA2D(lB, aB, c04, lB);
                FFMA2(pA2, lA, avp[i]);    FFMA2(pB2, lB, avp[i]);
            }
            float pA = f2lo(pA2) + f2hi(pA2);
            float pB = f2lo(pB2) + f2hi(pB2);
            pA += __shfl_xor_sync(0xffffffffu, pA, 1);
            pB += __shfl_xor_sync(0xffffffffu, pB, 1);
            pA += __shfl_xor_sync(0xffffffffu, pA, 2);
            pB += __shfl_xor_sync(0xffffffffu, pB, 2);
            pA += __shfl_xor_sync(0xffffffffu, pA, 4);
            pB += __shfl_xor_sync(0xffffffffu, pB, 4);
            float exA = __expf(pA);
            float exB = __expf(pB);
            den += exA;
            ull dA; DUP2(dA, exA);
            #pragma unroll
            for (int i = 0; i < 4; i++) FFMA2(acc[i], xA[i], dA);
            if (hasB) {
                den += exB;
                ull dB; DUP2(dB, exB);
                #pragma unroll
                for (int i = 0; i < 4; i++) FFMA2(acc[i], xB[i], dB);
            }
            hA = hA2; hB = hB2;
            e += 2;
        }

        float inv = 1.f / (den + 1e-16f);
        float a8[8];
        #pragma unroll
        for (int i = 0; i < 4; i++) {
            a8[2*i]   = f2lo(acc[i]) * inv;
            a8[2*i+1] = f2hi(acc[i]) * inv;
        }
        #pragma unroll
        for (int j = 0; j < 8; j++) {
            float v = a8[j];
            v += __shfl_xor_sync(0xffffffffu, v, 8);
            v += __shfl_xor_sync(0xffffffffu, v, 16);
            a8[j] = v;
        }
        if (lane < 8) {
            float o0 = fmaxf(a8[0] * 0.25f + bv0.x, 0.f);
            float o1 = fmaxf(a8[1] * 0.25f + bv0.y, 0.f);
            float o2 = fmaxf(a8[2] * 0.25f + bv0.z, 0.f);
            float o3 = fmaxf(a8[3] * 0.25f + bv0.w, 0.f);
            float o4 = fmaxf(a8[4] * 0.25f + bv1.x, 0.f);
            float o5 = fmaxf(a8[5] * 0.25f + bv1.y, 0.f);
            float o6 = fmaxf(a8[6] * 0.25f + bv1.z, 0.f);
            float o7 = fmaxf(a8[7] * 0.25f + bv1.w, 0.f);
            float* hp = g_h + (size_t)n * HID + 8 * lane;
            *(float4*)hp       = make_float4(o0, o1, o2, o3);
            *(float4*)(hp + 4) = make_float4(o4, o5, o6, o7);
        }
    }
}

// ---------------- graph pooling -------------------------------------------------
__global__ void pool_kernel(const int* __restrict__ batch) {
    int idx = blockIdx.x * blockDim.x + threadIdx.x;
    if (idx >= NN * HID) return;
    int n = idx >> 6, c = idx & 63;
    int g = batch[n];
    atomicAdd(&g_pool[g * HID + c], g_h[idx]);
    if (c == 0) atomicAdd(&g_cnt[g], 1.f);
}

// ---------------- head ----------------------------------------------------------
__global__ __launch_bounds__(64) void final_kernel(
        const float* __restrict__ W_fc, const float* __restrict__ b_fc,
        const float* __restrict__ W_res, const float* __restrict__ b_res,
        const float* __restrict__ W_time, const float* __restrict__ b_time,
        float* __restrict__ out) {
    int g = blockIdx.x;
    int c = threadIdx.x;
    float inv = 1.f / fmaxf(g_cnt[g], 1.f);
    float acc = b_fc[c];
    for (int k = 0; k < HID; k++)
        acc = fmaf(g_pool[g * HID + k] * inv, W_fc[k * HID + c], acc);
    float gv = (acc > 0.f) ? acc : 0.f;
    float r  = gv * W_res[c];
    float tm = gv * W_time[c];
    #pragma unroll
    for (int o = 16; o; o >>= 1) {
        r  += __shfl_xor_sync(0xffffffffu, r, o);
        tm += __shfl_xor_sync(0xffffffffu, tm, o);
    }
    __shared__ float sr[2], st[2];
    if ((c & 31) == 0) { sr[c >> 5] = r; st[c >> 5] = tm; }
    __syncthreads();
    if (c == 0) {
        out[g * 2 + 0] = sr[0] + sr[1] + b_res[0];
        out[g * 2 + 1] = st[0] + st[1] + b_time[0];
    }
}

// ---------------- cleanup: restore zeroed state for the next replay -------------
__global__ void cleanup_kernel() {
    int idx = blockIdx.x * blockDim.x + threadIdx.x;
    int stride = gridDim.x * blockDim.x;
    for (int i = idx; i < NN; i += stride) g_hist[i] = 0;
    for (int i = idx; i < GG * HID; i += stride) g_pool[i] = 0.f;
    for (int i = idx; i < GG; i += stride) g_cnt[i] = 0.f;
}

// ---------------- launcher -------------------------------------------------------
extern "C" void kernel_launch(void* const* d_in, const int* in_sizes, int n_in,
                              void* d_out, int out_size) {
    int I_x, I_ea, I_ei, I_b, I_Wet, I_bet, I_Wuw, I_buw, I_Wua, I_bua;
    int I_Wl0, I_bl0, I_Wr0, I_br0, I_att0, I_We0, I_bias0;
    int I_Wl1, I_bl1, I_Wr1, I_br1, I_att1, I_We1, I_bias1;
    int I_Wfc, I_bfc, I_Wres, I_bres, I_Wtime, I_btime;
    if (in_sizes[0] == 2) {
        I_Wet = 0; I_Wfc = 1; I_Wres = 2; I_Wtime = 3; I_Wua = 4; I_Wuw = 5;
        I_We0 = 6; I_We1 = 7; I_Wl0 = 8; I_Wl1 = 9; I_Wr0 = 10; I_Wr1 = 11;
        I_att0 = 12; I_att1 = 13;
        I_bet = 14; I_bfc = 15; I_bres = 16; I_btime = 17; I_bua = 18; I_buw = 19;
        I_b = 20; I_bias0 = 21; I_bias1 = 22;
        I_bl0 = 23; I_bl1 = 24; I_br0 = 25; I_br1 = 26;
        I_ea = 27; I_ei = 28; I_x = 29;
    } else if (in_sizes[2] == 2 * EE) {
        I_x = 0; I_ea = 1; I_ei = 2; I_b = 3;
        I_Wet = 4; I_bet = 5; I_Wuw = 6; I_buw = 7; I_Wua = 8; I_bua = 9;
        I_Wl0 = 10; I_bl0 = 11; I_Wr0 = 12; I_br0 = 13; I_att0 = 14; I_We0 = 15; I_bias0 = 16;
        I_Wl1 = 17; I_bl1 = 18; I_Wr1 = 19; I_br1 = 20; I_att1 = 21; I_We1 = 22; I_bias1 = 23;
        I_Wfc = 24; I_bfc = 25; I_Wres = 26; I_bres = 27; I_Wtime = 28; I_btime = 29;
    } else {
        I_x = 0; I_ea = 1;
        I_Wet = 2; I_bet = 3; I_Wuw = 4; I_buw = 5; I_Wua = 6; I_bua = 7;
        I_Wl0 = 8; I_bl0 = 9; I_Wr0 = 10; I_br0 = 11; I_att0 = 12; I_We0 = 13; I_bias0 = 14;
        I_Wl1 = 15; I_bl1 = 16; I_Wr1 = 17; I_br1 = 18; I_att1 = 19; I_We1 = 20; I_bias1 = 21;
        I_Wfc = 22; I_bfc = 23; I_Wres = 24; I_bres = 25; I_Wtime = 26; I_btime = 27;
        I_ei = 28; I_b = 29;
    }

    const float* x        = (const float*)d_in[I_x];
    const float* edge_attr= (const float*)d_in[I_ea];
    const int*   edge_idx = (const int*)  d_in[I_ei];
    const int*   batch    = (const int*)  d_in[I_b];
    const float* W_et = (const float*)d_in[I_Wet], *b_et = (const float*)d_in[I_bet];
    const float* W_uw = (const float*)d_in[I_Wuw], *b_uw = (const float*)d_in[I_buw];
    const float* W_ua = (const float*)d_in[I_Wua], *b_ua = (const float*)d_in[I_bua];
    const float* Wl0 = (const float*)d_in[I_Wl0], *bl0 = (const float*)d_in[I_bl0];
    const float* Wr0 = (const float*)d_in[I_Wr0], *br0 = (const float*)d_in[I_br0];
    const float* att0 = (const float*)d_in[I_att0], *We0 = (const float*)d_in[I_We0];
    const float* bias0 = (const float*)d_in[I_bias0];
    const float* Wl1 = (const float*)d_in[I_Wl1], *bl1 = (const float*)d_in[I_bl1];
    const float* Wr1 = (const float*)d_in[I_Wr1], *br1 = (const float*)d_in[I_br1];
    const float* att1 = (const float*)d_in[I_att1], *We1 = (const float*)d_in[I_We1];
    const float* bias1 = (const float*)d_in[I_bias1];
    const float* W_fc = (const float*)d_in[I_Wfc], *b_fc = (const float*)d_in[I_bfc];
    const float* W_res = (const float*)d_in[I_Wres], *b_res = (const float*)d_in[I_bres];
    const float* W_time = (const float*)d_in[I_Wtime], *b_time = (const float*)d_in[I_btime];
    float* out = (float*)d_out;

    // launch order: position 4 is the ncu-profiled launch -> edge_kernel layer 0.
    hist_kernel<<<(EE + 255) / 256, 256>>>(edge_idx);                 // 1
    gemm_scan_kernel<<<NN / 16 + 1, 256>>>(x, Wl0, bl0, Wr0, br0);    // 2 (GEMM0 + scan)
    scatter_kernel<<<(EE + 255) / 256, 256>>>(edge_idx, edge_attr,    // 3
                                              W_et, b_et, W_uw, b_uw, W_ua, b_ua);
    edge_kernel<<<EDGE_BLOCKS, 256>>>(att0, We0, bias0);              // 4  <- profiled
    gemm_f2_kernel1<<<NN / 16, 256>>>(Wl1, bl1, Wr1, br1);            // 5
    edge_kernel<<<EDGE_BLOCKS, 256>>>(att1, We1, bias1);              // 6
    pool_kernel<<<(NN * HID + 255) / 256, 256>>>(batch);              // 7
    final_kernel<<<GG, 64>>>(W_fc, b_fc, W_res, b_res, W_time, b_time, out); // 8
    cleanup_kernel<<<128, 256>>>();                                   // 9
}